// round 9
// baseline (speedup 1.0000x reference)
#include <cuda_runtime.h>
#include <cuda_fp16.h>
#include <cstddef>
#include <cstdint>

// ---------------------------------------------------------------------------
// GCN 3-layer encoder, fp16 pipeline, forked-graph schedule.
//   main stream : prep (W^T + x->fp16) -> GEMM1 (unscaled h = X@W1)
//   side stream : zero_deg -> hist -> dinv -> scan -> scatter   (CSR build)
//   join        : agg1 (dinv_src-weighted) -> GEMM2 -> agg2 -> GEMM3 -> agg3
// Persistent-block GEMM, cp.async double-buffered X tiles, ldmatrix+MMA.
// ---------------------------------------------------------------------------

#define N_MAX 100000
#define E_MAX 1600000
#define SCAN_B 1024
#define MAX_SCAN_BLOCKS 128

__device__ __half x16_buf[(size_t)N_MAX * 128];
__device__ __half g_buf[(size_t)N_MAX * 128];
__device__ __half agg_buf[(size_t)N_MAX * 128];
__device__ float dinv_buf[N_MAX];
__device__ int   deg_buf[N_MAX];
__device__ int   rowptr_buf[N_MAX + 1];
__device__ int   cursor_buf[N_MAX];
__device__ int   csrsrc_buf[E_MAX];
__device__ int   blocksum_buf[MAX_SCAN_BLOCKS];
__device__ __half wt1_buf[128 * 128];
__device__ __half wt2_buf[128 * 128];
__device__ __half wt3_buf[64 * 128];

// ---------------- prep: W transpose + x -> fp16 (NO deg work) ---------------

__global__ void k_prep(const float* __restrict__ x, const float* __restrict__ W1,
                       const float* __restrict__ W2, const float* __restrict__ W3,
                       int n) {
    int tid = blockIdx.x * blockDim.x + threadIdx.x;
    int nth = gridDim.x * blockDim.x;
    if (tid < 128 * 128) {
        int k = tid >> 7, c = tid & 127;
        wt1_buf[c * 128 + k] = __float2half_rn(__ldg(&W1[tid]));
        wt2_buf[c * 128 + k] = __float2half_rn(__ldg(&W2[tid]));
    }
    if (tid < 128 * 64) {
        int k = tid >> 6, c = tid & 63;
        wt3_buf[c * 128 + k] = __float2half_rn(__ldg(&W3[tid]));
    }
    int xq = n * 16;   // n*128/8
    for (int i = tid; i < xq; i += nth) {
        const float* xp = x + (size_t)i * 8;
        float4 v0 = __ldg((const float4*)xp);
        float4 v1 = __ldg((const float4*)(xp + 4));
        half2 h0 = __floats2half2_rn(v0.x, v0.y);
        half2 h1 = __floats2half2_rn(v0.z, v0.w);
        half2 h2 = __floats2half2_rn(v1.x, v1.y);
        half2 h3 = __floats2half2_rn(v1.z, v1.w);
        uint4 u = make_uint4(*(uint32_t*)&h0, *(uint32_t*)&h1,
                             *(uint32_t*)&h2, *(uint32_t*)&h3);
        *(uint4*)(x16_buf + (size_t)i * 8) = u;
    }
}

// -------------------------------- CSR prep --------------------------------

__global__ void k_zero_deg(int n) {
    int i = blockIdx.x * blockDim.x + threadIdx.x;
    if (i < n) deg_buf[i] = 0;
}

__global__ void k_hist(const int* __restrict__ dst, int e) {
    int i = blockIdx.x * blockDim.x + threadIdx.x;
    if (i < e) atomicAdd(&deg_buf[dst[i]], 1);
}

__global__ void k_dinv(int n) {
    int i = blockIdx.x * blockDim.x + threadIdx.x;
    if (i < n) dinv_buf[i] = rsqrtf((float)deg_buf[i] + 1.0f);
}

__global__ __launch_bounds__(SCAN_B) void k_blocksum(int n) {
    __shared__ int wsum[32];
    int i = blockIdx.x * SCAN_B + threadIdx.x;
    int v = (i < n) ? deg_buf[i] : 0;
    #pragma unroll
    for (int off = 16; off > 0; off >>= 1)
        v += __shfl_down_sync(0xffffffffu, v, off);
    int lane = threadIdx.x & 31, w = threadIdx.x >> 5;
    if (lane == 0) wsum[w] = v;
    __syncthreads();
    if (w == 0) {
        int s = wsum[lane];
        #pragma unroll
        for (int off = 16; off > 0; off >>= 1)
            s += __shfl_down_sync(0xffffffffu, s, off);
        if (lane == 0) blocksum_buf[blockIdx.x] = s;
    }
}

__global__ void k_scan_blocksums(int nblocks, int n, int e) {
    __shared__ int wsum[4];
    int t = threadIdx.x;
    int v = (t < nblocks) ? blocksum_buf[t] : 0;
    int lane = t & 31, w = t >> 5;
    int s = v;
    #pragma unroll
    for (int off = 1; off < 32; off <<= 1) {
        int x = __shfl_up_sync(0xffffffffu, s, off);
        if (lane >= off) s += x;
    }
    if (lane == 31) wsum[w] = s;
    __syncthreads();
    int base = 0;
    #pragma unroll
    for (int k = 0; k < 4; k++) base += (k < w) ? wsum[k] : 0;
    if (t < nblocks) blocksum_buf[t] = base + s - v;
    if (t == 0) rowptr_buf[n] = e;
}

__global__ __launch_bounds__(SCAN_B) void k_block_scan(int n) {
    __shared__ int wsum[32];
    int i = blockIdx.x * SCAN_B + threadIdx.x;
    int v = (i < n) ? deg_buf[i] : 0;
    int lane = threadIdx.x & 31, w = threadIdx.x >> 5;
    int s = v;
    #pragma unroll
    for (int off = 1; off < 32; off <<= 1) {
        int x = __shfl_up_sync(0xffffffffu, s, off);
        if (lane >= off) s += x;
    }
    if (lane == 31) wsum[w] = s;
    __syncthreads();
    if (w == 0) {
        int ws = wsum[lane];
        #pragma unroll
        for (int off = 1; off < 32; off <<= 1) {
            int x = __shfl_up_sync(0xffffffffu, ws, off);
            if (lane >= off) ws += x;
        }
        wsum[lane] = ws;
    }
    __syncthreads();
    int warpBase = (w > 0) ? wsum[w - 1] : 0;
    if (i < n) {
        int p = blocksum_buf[blockIdx.x] + warpBase + (s - v);
        rowptr_buf[i] = p;
        cursor_buf[i] = p;
    }
}

__global__ void k_scatter(const int* __restrict__ src, const int* __restrict__ dst, int e) {
    int i = blockIdx.x * blockDim.x + threadIdx.x;
    if (i < e) {
        int d = dst[i];
        int pos = atomicAdd(&cursor_buf[d], 1);
        csrsrc_buf[pos] = src[i];
    }
}

// ----------------------- fp16 tensor-core GEMM -----------------------------
// Persistent blocks; W staged once; X tiles double-buffered via cp.async.
// SCALE: multiply output rows by dinv[row] (layers 2,3). Layer 1: off.

__device__ __forceinline__ void ldsm_x4(uint32_t& r0, uint32_t& r1,
                                        uint32_t& r2, uint32_t& r3, uint32_t addr) {
    asm volatile("ldmatrix.sync.aligned.m8n8.x4.shared.b16 {%0,%1,%2,%3}, [%4];"
                 : "=r"(r0), "=r"(r1), "=r"(r2), "=r"(r3) : "r"(addr));
}

template <int DOUT, bool SCALE>
__global__ __launch_bounds__(256) void k_gemm_tc(const __half* __restrict__ X,
                                                 const __half* __restrict__ Wt,
                                                 __half* __restrict__ G,
                                                 int n, int tiles) {
    constexpr int DIN = 128;
    constexpr int WN = DOUT / 32;
    constexpr int WM = 8 / WN;
    constexpr int MB = WM * 32;
    constexpr int XS = 136;
    constexpr int WKS = 136;
    constexpr int XTILE = MB * XS;

    extern __shared__ __half hsm[];
    __half* Ws = hsm;
    __half* Xb[2] = { hsm + DOUT * WKS, hsm + DOUT * WKS + XTILE };

    int t = threadIdx.x;
    int warp = t >> 5, lane = t & 31;
    int wm = warp / WN, wn = warp % WN;
    int g = lane >> 2, tg = lane & 3;

    #pragma unroll
    for (int i = t * 8; i < DOUT * DIN; i += 256 * 8) {
        int c = i >> 7, k = i & 127;
        uint4 v = __ldg((const uint4*)(Wt + i));
        *(uint4*)&Ws[c * WKS + k] = v;
    }

    auto stage = [&](int tile, __half* buf) {
        int rowBase = tile * MB;
        #pragma unroll
        for (int i = t * 8; i < MB * DIN; i += 256 * 8) {
            int r = i >> 7, c = i & 127;
            int row = rowBase + r;
            uint32_t saddr = (uint32_t)__cvta_generic_to_shared(&buf[r * XS + c]);
            const __half* gp = X + (size_t)(row < n ? row : 0) * DIN + c;
            int sz = (row < n) ? 16 : 0;
            asm volatile("cp.async.cg.shared.global [%0], [%1], 16, %2;"
                         :: "r"(saddr), "l"(gp), "r"(sz) : "memory");
        }
        asm volatile("cp.async.commit_group;" ::: "memory");
    };

    uint32_t ws_base = (uint32_t)__cvta_generic_to_shared(Ws);
    uint32_t b_addr = ws_base + (uint32_t)(((wn * 32 + lane) * WKS) * 2);

    int tile = blockIdx.x;
    if (tile < tiles) stage(tile, Xb[0]);
    int cur = 0;

    for (; tile < tiles; tile += gridDim.x) {
        int nxt = tile + gridDim.x;
        if (nxt < tiles) stage(nxt, Xb[cur ^ 1]);

        if (nxt < tiles)
            asm volatile("cp.async.wait_group 1;" ::: "memory");
        else
            asm volatile("cp.async.wait_group 0;" ::: "memory");
        __syncthreads();

        __half* Xs = Xb[cur];
        uint32_t xs_base = (uint32_t)__cvta_generic_to_shared(Xs);
        uint32_t a_addr0 = xs_base + (uint32_t)(((wm * 32 + (lane & 15)) * XS + ((lane >> 4) << 3)) * 2);
        uint32_t a_addr1 = a_addr0 + (uint32_t)(16 * XS * 2);

        float acc[2][4][4];
        #pragma unroll
        for (int a = 0; a < 2; a++)
            #pragma unroll
            for (int u = 0; u < 4; u++)
                #pragma unroll
                for (int k = 0; k < 4; k++) acc[a][u][k] = 0.f;

        #pragma unroll
        for (int ks = 0; ks < DIN / 16; ks++) {
            uint32_t koff = (uint32_t)(ks * 16 * 2);
            uint32_t a[2][4], b0[4], b1[4];
            ldsm_x4(a[0][0], a[0][1], a[0][2], a[0][3], a_addr0 + koff);
            ldsm_x4(a[1][0], a[1][1], a[1][2], a[1][3], a_addr1 + koff);
            ldsm_x4(b0[0], b0[1], b0[2], b0[3], b_addr + koff);
            ldsm_x4(b1[0], b1[1], b1[2], b1[3], b_addr + koff + 16);
            #pragma unroll
            for (int tt = 0; tt < 2; tt++)
                #pragma unroll
                for (int u = 0; u < 4; u++) {
                    asm volatile(
                        "mma.sync.aligned.m16n8k16.row.col.f32.f16.f16.f32 "
                        "{%0,%1,%2,%3}, {%4,%5,%6,%7}, {%8,%9}, {%0,%1,%2,%3};"
                        : "+f"(acc[tt][u][0]), "+f"(acc[tt][u][1]),
                          "+f"(acc[tt][u][2]), "+f"(acc[tt][u][3])
                        : "r"(a[tt][0]), "r"(a[tt][1]), "r"(a[tt][2]), "r"(a[tt][3]),
                          "r"(b0[u]), "r"(b1[u]));
                }
        }

        int rowBase = tile * MB;
        #pragma unroll
        for (int tt = 0; tt < 2; tt++) {
            int r0 = rowBase + wm * 32 + tt * 16 + g;
            int r1 = r0 + 8;
            int cbase = wn * 32 + 2 * tg;
            if (r0 < n) {
                float di = SCALE ? dinv_buf[r0] : 1.0f;
                #pragma unroll
                for (int u = 0; u < 4; u++) {
                    half2 h = __floats2half2_rn(acc[tt][u][0] * di, acc[tt][u][1] * di);
                    *(half2*)(G + (size_t)r0 * DOUT + cbase + u * 8) = h;
                }
            }
            if (r1 < n) {
                float di = SCALE ? dinv_buf[r1] : 1.0f;
                #pragma unroll
                for (int u = 0; u < 4; u++) {
                    half2 h = __floats2half2_rn(acc[tt][u][2] * di, acc[tt][u][3] * di);
                    *(half2*)(G + (size_t)r1 * DOUT + cbase + u * 8) = h;
                }
            }
        }
        __syncthreads();
        cur ^= 1;
    }
}

// ------------------------------ Aggregation --------------------------------
// SRCW: rows of G are unscaled h; weight each gathered row by dinv[src] and
// the self row by dinv_i (then the whole sum by dinv_i). Otherwise G rows are
// already g = dinv*h and weights are 1.

template <int D, bool RELU, bool SRCW, typename TOUT>
__global__ __launch_bounds__(256) void k_aggregate(const __half* __restrict__ G,
                                                   const float* __restrict__ bias,
                                                   TOUT* __restrict__ OUT, int n) {
    int wid = (blockIdx.x * blockDim.x + threadIdx.x) >> 5;
    int lane = threadIdx.x & 31;
    if (wid >= n) return;
    constexpr int V = D / 32;

    float di = dinv_buf[wid];
    float selfw = SRCW ? di : 1.0f;

    float acc[V];
    if constexpr (V == 4) {
        uint2 a = *(const uint2*)(G + (size_t)wid * D + lane * 4);
        float2 f0 = __half22float2(*(half2*)&a.x);
        float2 f1 = __half22float2(*(half2*)&a.y);
        acc[0] = selfw * f0.x; acc[1] = selfw * f0.y;
        acc[2] = selfw * f1.x; acc[3] = selfw * f1.y;
    } else {
        uint32_t a = *(const uint32_t*)(G + (size_t)wid * D + lane * 2);
        float2 f = __half22float2(*(half2*)&a);
        acc[0] = selfw * f.x; acc[1] = selfw * f.y;
    }

    int s0 = rowptr_buf[wid];
    int s1 = rowptr_buf[wid + 1];

    int j = s0;
    for (; j + 3 < s1; j += 4) {
        int sa = __ldg(&csrsrc_buf[j]);
        int sb = __ldg(&csrsrc_buf[j + 1]);
        int sc = __ldg(&csrsrc_buf[j + 2]);
        int sd = __ldg(&csrsrc_buf[j + 3]);
        float wa = SRCW ? __ldg(&dinv_buf[sa]) : 1.0f;
        float wb = SRCW ? __ldg(&dinv_buf[sb]) : 1.0f;
        float wc = SRCW ? __ldg(&dinv_buf[sc]) : 1.0f;
        float wd = SRCW ? __ldg(&dinv_buf[sd]) : 1.0f;
        if constexpr (V == 4) {
            uint2 a = __ldg((const uint2*)(G + (size_t)sa * D) + lane);
            uint2 b = __ldg((const uint2*)(G + (size_t)sb * D) + lane);
            uint2 c = __ldg((const uint2*)(G + (size_t)sc * D) + lane);
            uint2 d = __ldg((const uint2*)(G + (size_t)sd * D) + lane);
            float2 fa0 = __half22float2(*(half2*)&a.x), fa1 = __half22float2(*(half2*)&a.y);
            float2 fb0 = __half22float2(*(half2*)&b.x), fb1 = __half22float2(*(half2*)&b.y);
            float2 fc0 = __half22float2(*(half2*)&c.x), fc1 = __half22float2(*(half2*)&c.y);
            float2 fd0 = __half22float2(*(half2*)&d.x), fd1 = __half22float2(*(half2*)&d.y);
            acc[0] += wa * fa0.x + wb * fb0.x + wc * fc0.x + wd * fd0.x;
            acc[1] += wa * fa0.y + wb * fb0.y + wc * fc0.y + wd * fd0.y;
            acc[2] += wa * fa1.x + wb * fb1.x + wc * fc1.x + wd * fd1.x;
            acc[3] += wa * fa1.y + wb * fb1.y + wc * fc1.y + wd * fd1.y;
        } else {
            uint32_t a = __ldg((const uint32_t*)(G + (size_t)sa * D) + lane);
            uint32_t b = __ldg((const uint32_t*)(G + (size_t)sb * D) + lane);
            uint32_t c = __ldg((const uint32_t*)(G + (size_t)sc * D) + lane);
            uint32_t d = __ldg((const uint32_t*)(G + (size_t)sd * D) + lane);
            float2 fa = __half22float2(*(half2*)&a);
            float2 fb = __half22float2(*(half2*)&b);
            float2 fc = __half22float2(*(half2*)&c);
            float2 fd = __half22float2(*(half2*)&d);
            acc[0] += wa * fa.x + wb * fb.x + wc * fc.x + wd * fd.x;
            acc[1] += wa * fa.y + wb * fb.y + wc * fc.y + wd * fd.y;
        }
    }
    for (; j < s1; j++) {
        int s = __ldg(&csrsrc_buf[j]);
        float ws = SRCW ? __ldg(&dinv_buf[s]) : 1.0f;
        if constexpr (V == 4) {
            uint2 a = __ldg((const uint2*)(G + (size_t)s * D) + lane);
            float2 f0 = __half22float2(*(half2*)&a.x), f1 = __half22float2(*(half2*)&a.y);
            acc[0] += ws * f0.x; acc[1] += ws * f0.y;
            acc[2] += ws * f1.x; acc[3] += ws * f1.y;
        } else {
            uint32_t a = __ldg((const uint32_t*)(G + (size_t)s * D) + lane);
            float2 f = __half22float2(*(half2*)&a);
            acc[0] += ws * f.x; acc[1] += ws * f.y;
        }
    }

    if constexpr (V == 4) {
        float4 b = __ldg((const float4*)bias + lane);
        float o0 = acc[0] * di + b.x, o1 = acc[1] * di + b.y;
        float o2 = acc[2] * di + b.z, o3 = acc[3] * di + b.w;
        if (RELU) {
            o0 = fmaxf(o0, 0.f); o1 = fmaxf(o1, 0.f);
            o2 = fmaxf(o2, 0.f); o3 = fmaxf(o3, 0.f);
        }
        if constexpr (sizeof(TOUT) == 2) {
            __half* op = (__half*)OUT + (size_t)wid * D + lane * 4;
            *(half2*)op = __floats2half2_rn(o0, o1);
            *(half2*)(op + 2) = __floats2half2_rn(o2, o3);
        } else {
            float* op = (float*)OUT + (size_t)wid * D + lane * 4;
            *(float4*)op = make_float4(o0, o1, o2, o3);
        }
    } else {
        float2 b = __ldg((const float2*)bias + lane);
        float o0 = acc[0] * di + b.x, o1 = acc[1] * di + b.y;
        if (RELU) { o0 = fmaxf(o0, 0.f); o1 = fmaxf(o1, 0.f); }
        if constexpr (sizeof(TOUT) == 2) {
            __half* op = (__half*)OUT + (size_t)wid * D + lane * 2;
            *(half2*)op = __floats2half2_rn(o0, o1);
        } else {
            float* op = (float*)OUT + (size_t)wid * D + lane * 2;
            *(float2*)op = make_float2(o0, o1);
        }
    }
}

// ------------------------------- launch ------------------------------------

extern "C" void kernel_launch(void* const* d_in, const int* in_sizes, int n_in,
                              void* d_out, int out_size) {
    const float* x  = (const float*)d_in[0];
    const int*   ei = (const int*)d_in[1];
    const float* W1 = (const float*)d_in[2];
    const float* b1 = (const float*)d_in[3];
    const float* W2 = (const float*)d_in[4];
    const float* b2 = (const float*)d_in[5];
    const float* W3 = (const float*)d_in[6];
    const float* b3 = (const float*)d_in[7];

    int n = in_sizes[0] / 128;
    int e = in_sizes[1] / 2;
    const int* src = ei;
    const int* dst = ei + e;

    __half *x16, *g, *agg, *wt1, *wt2, *wt3;
    cudaGetSymbolAddress((void**)&x16, x16_buf);
    cudaGetSymbolAddress((void**)&g, g_buf);
    cudaGetSymbolAddress((void**)&agg, agg_buf);
    cudaGetSymbolAddress((void**)&wt1, wt1_buf);
    cudaGetSymbolAddress((void**)&wt2, wt2_buf);
    cudaGetSymbolAddress((void**)&wt3, wt3_buf);
    float* out = (float*)d_out;

    int nb = (n + 255) / 256;
    int eb = (e + 255) / 256;
    int scan_blocks = (n + SCAN_B - 1) / SCAN_B;

    constexpr int SMEM128 = (128 * 136 + 2 * 64 * 136) * 2;
    constexpr int SMEM64  = (64 * 136 + 2 * 128 * 136) * 2;
    cudaFuncSetAttribute(k_gemm_tc<128, false>, cudaFuncAttributeMaxDynamicSharedMemorySize, SMEM128);
    cudaFuncSetAttribute(k_gemm_tc<128, true>,  cudaFuncAttributeMaxDynamicSharedMemorySize, SMEM128);
    cudaFuncSetAttribute(k_gemm_tc<64,  true>,  cudaFuncAttributeMaxDynamicSharedMemorySize, SMEM64);

    int tiles128 = (n + 63) / 64;
    int tiles64  = (n + 127) / 128;
    int grid128 = tiles128 < 444 ? tiles128 : 444;
    int grid64  = tiles64  < 296 ? tiles64  : 296;

    // One-time side stream + fork/join events (host infra; first call is the
    // uncaptured correctness run, so creation never happens during capture).
    static cudaStream_t s_side = [] {
        cudaStream_t s; cudaStreamCreateWithFlags(&s, cudaStreamNonBlocking); return s;
    }();
    static cudaEvent_t ev_fork = [] {
        cudaEvent_t ev; cudaEventCreateWithFlags(&ev, cudaEventDisableTiming); return ev;
    }();
    static cudaEvent_t ev_join = [] {
        cudaEvent_t ev; cudaEventCreateWithFlags(&ev, cudaEventDisableTiming); return ev;
    }();

    // ---- fork ----
    k_prep<<<400, 256>>>(x, W1, W2, W3, n);                         // launch 1 (main)
    cudaEventRecord(ev_fork, 0);
    cudaStreamWaitEvent(s_side, ev_fork, 0);

    k_zero_deg<<<nb, 256, 0, s_side>>>(n);                          // launch 2 (side)
    k_hist<<<eb, 256, 0, s_side>>>(dst, e);                         // launch 3 (side)

    // Layer-1 GEMM (unscaled) in parallel with CSR chain. Launch 4 for ncu.
    k_gemm_tc<128, false><<<grid128, 256, SMEM128>>>(x16, wt1, g, n, tiles128);

    k_dinv<<<nb, 256, 0, s_side>>>(n);
    k_blocksum<<<scan_blocks, SCAN_B, 0, s_side>>>(n);
    k_scan_blocksums<<<1, MAX_SCAN_BLOCKS, 0, s_side>>>(scan_blocks, n, e);
    k_block_scan<<<scan_blocks, SCAN_B, 0, s_side>>>(n);
    k_scatter<<<eb, 256, 0, s_side>>>(src, dst, e);
    cudaEventRecord(ev_join, s_side);
    cudaStreamWaitEvent(0, ev_join, 0);
    // ---- joined: everything below on the main stream ----

    int agg_blocks = (n * 32 + 255) / 256;

    // Layer 1 aggregation: source-weighted (h rows unscaled).
    k_aggregate<128, true, true, __half><<<agg_blocks, 256>>>(g, b1, agg, n);

    k_gemm_tc<128, true><<<grid128, 256, SMEM128>>>(agg, wt2, g, n, tiles128);
    k_aggregate<128, true, false, __half><<<agg_blocks, 256>>>(g, b2, agg, n);

    k_gemm_tc<64, true><<<grid64, 256, SMEM64>>>(agg, wt3, g, n, tiles64);
    k_aggregate<64, false, false, float><<<agg_blocks, 256>>>(g, b3, out, n);
}

// round 10
// speedup vs baseline: 1.0838x; 1.0838x over previous
#include <cuda_runtime.h>
#include <cuda_fp16.h>
#include <cstddef>
#include <cstdint>

// ---------------------------------------------------------------------------
// GCN 3-layer encoder, fp16 pipeline, single-stream schedule.
//   per layer: g = (act(in) @ W) * dinv[row]   (fp16 MMA, fp32 accum)
//              out_i = dinv_i * (sum_{e: dst=i} g[src_e] + g_i) + b  [+ReLU]
// Persistent-block GEMMs (W staged once/block). Layer 1 stages fp32->fp16
// inline; layers 2/3 use cp.async double-buffered fp16 tiles.
// ---------------------------------------------------------------------------

#define N_MAX 100000
#define E_MAX 1600000
#define SCAN_B 1024
#define MAX_SCAN_BLOCKS 128

__device__ __half g_buf[(size_t)N_MAX * 128];
__device__ __half agg_buf[(size_t)N_MAX * 128];
__device__ float dinv_buf[N_MAX];
__device__ int   deg_buf[N_MAX];
__device__ int   rowptr_buf[N_MAX + 1];
__device__ int   cursor_buf[N_MAX];
__device__ int   csrsrc_buf[E_MAX];
__device__ int   blocksum_buf[MAX_SCAN_BLOCKS];
__device__ __half wt1_buf[128 * 128];
__device__ __half wt2_buf[128 * 128];
__device__ __half wt3_buf[64 * 128];

// ---------------- prep: zero deg + W transposes -----------------------------

__global__ void k_prep(const float* __restrict__ W1, const float* __restrict__ W2,
                       const float* __restrict__ W3, int n) {
    int i = blockIdx.x * blockDim.x + threadIdx.x;
    if (i < n) deg_buf[i] = 0;
    if (i < 128 * 128) {
        int k = i >> 7, c = i & 127;
        wt1_buf[c * 128 + k] = __float2half_rn(__ldg(&W1[i]));
        wt2_buf[c * 128 + k] = __float2half_rn(__ldg(&W2[i]));
    }
    if (i < 128 * 64) {
        int k = i >> 6, c = i & 63;
        wt3_buf[c * 128 + k] = __float2half_rn(__ldg(&W3[i]));
    }
}

// -------------------------------- CSR prep --------------------------------

__global__ void k_hist(const int* __restrict__ dst, int e) {
    int i = blockIdx.x * blockDim.x + threadIdx.x;
    if (i < e) atomicAdd(&deg_buf[dst[i]], 1);
}

// Fused: dinv[i] = rsqrt(deg+1), and per-block sum of deg for the scan.
__global__ __launch_bounds__(SCAN_B) void k_blocksum_dinv(int n) {
    __shared__ int wsum[32];
    int i = blockIdx.x * SCAN_B + threadIdx.x;
    int v = 0;
    if (i < n) {
        v = deg_buf[i];
        dinv_buf[i] = rsqrtf((float)v + 1.0f);
    }
    int s = v;
    #pragma unroll
    for (int off = 16; off > 0; off >>= 1)
        s += __shfl_down_sync(0xffffffffu, s, off);
    int lane = threadIdx.x & 31, w = threadIdx.x >> 5;
    if (lane == 0) wsum[w] = s;
    __syncthreads();
    if (w == 0) {
        int t = wsum[lane];
        #pragma unroll
        for (int off = 16; off > 0; off >>= 1)
            t += __shfl_down_sync(0xffffffffu, t, off);
        if (lane == 0) blocksum_buf[blockIdx.x] = t;
    }
}

__global__ void k_scan_blocksums(int nblocks, int n, int e) {
    __shared__ int wsum[4];
    int t = threadIdx.x;
    int v = (t < nblocks) ? blocksum_buf[t] : 0;
    int lane = t & 31, w = t >> 5;
    int s = v;
    #pragma unroll
    for (int off = 1; off < 32; off <<= 1) {
        int x = __shfl_up_sync(0xffffffffu, s, off);
        if (lane >= off) s += x;
    }
    if (lane == 31) wsum[w] = s;
    __syncthreads();
    int base = 0;
    #pragma unroll
    for (int k = 0; k < 4; k++) base += (k < w) ? wsum[k] : 0;
    if (t < nblocks) blocksum_buf[t] = base + s - v;
    if (t == 0) rowptr_buf[n] = e;
}

__global__ __launch_bounds__(SCAN_B) void k_block_scan(int n) {
    __shared__ int wsum[32];
    int i = blockIdx.x * SCAN_B + threadIdx.x;
    int v = (i < n) ? deg_buf[i] : 0;
    int lane = threadIdx.x & 31, w = threadIdx.x >> 5;
    int s = v;
    #pragma unroll
    for (int off = 1; off < 32; off <<= 1) {
        int x = __shfl_up_sync(0xffffffffu, s, off);
        if (lane >= off) s += x;
    }
    if (lane == 31) wsum[w] = s;
    __syncthreads();
    if (w == 0) {
        int ws = wsum[lane];
        #pragma unroll
        for (int off = 1; off < 32; off <<= 1) {
            int x = __shfl_up_sync(0xffffffffu, ws, off);
            if (lane >= off) ws += x;
        }
        wsum[lane] = ws;
    }
    __syncthreads();
    int warpBase = (w > 0) ? wsum[w - 1] : 0;
    if (i < n) {
        int p = blocksum_buf[blockIdx.x] + warpBase + (s - v);
        rowptr_buf[i] = p;
        cursor_buf[i] = p;
    }
}

__global__ void k_scatter(const int* __restrict__ src, const int* __restrict__ dst, int e) {
    int i = blockIdx.x * blockDim.x + threadIdx.x;
    if (i < e) {
        int d = dst[i];
        int pos = atomicAdd(&cursor_buf[d], 1);
        csrsrc_buf[pos] = src[i];
    }
}

// ----------------------- fp16 tensor-core GEMM -----------------------------
// Persistent blocks; W staged once. TIN=half: cp.async double-buffered X.
// TIN=float: inline fp32->fp16 staging (single X buffer).

__device__ __forceinline__ void ldsm_x4(uint32_t& r0, uint32_t& r1,
                                        uint32_t& r2, uint32_t& r3, uint32_t addr) {
    asm volatile("ldmatrix.sync.aligned.m8n8.x4.shared.b16 {%0,%1,%2,%3}, [%4];"
                 : "=r"(r0), "=r"(r1), "=r"(r2), "=r"(r3) : "r"(addr));
}

template <int DOUT, typename TIN>
__global__ __launch_bounds__(256) void k_gemm_tc(const TIN* __restrict__ X,
                                                 const __half* __restrict__ Wt,
                                                 __half* __restrict__ G,
                                                 int n, int tiles) {
    constexpr bool HALF_IN = (sizeof(TIN) == 2);
    constexpr int DIN = 128;
    constexpr int WN = DOUT / 32;
    constexpr int WM = 8 / WN;
    constexpr int MB = WM * 32;
    constexpr int XS = 136;
    constexpr int WKS = 136;
    constexpr int XTILE = MB * XS;
    constexpr int NBUF = HALF_IN ? 2 : 1;

    extern __shared__ __half hsm[];
    __half* Ws = hsm;
    __half* Xb[2] = { hsm + DOUT * WKS,
                      hsm + DOUT * WKS + (NBUF == 2 ? XTILE : 0) };

    int t = threadIdx.x;
    int warp = t >> 5, lane = t & 31;
    int wm = warp / WN, wn = warp % WN;
    int g = lane >> 2, tg = lane & 3;

    // Stage W once.
    #pragma unroll
    for (int i = t * 8; i < DOUT * DIN; i += 256 * 8) {
        int c = i >> 7, k = i & 127;
        uint4 v = __ldg((const uint4*)(Wt + i));
        *(uint4*)&Ws[c * WKS + k] = v;
    }

    // fp16 cp.async staging.
    auto stage_async = [&](int tile, __half* buf) {
        int rowBase = tile * MB;
        #pragma unroll
        for (int i = t * 8; i < MB * DIN; i += 256 * 8) {
            int r = i >> 7, c = i & 127;
            int row = rowBase + r;
            uint32_t saddr = (uint32_t)__cvta_generic_to_shared(&buf[r * XS + c]);
            const __half* gp = (const __half*)X + (size_t)(row < n ? row : 0) * DIN + c;
            int sz = (row < n) ? 16 : 0;
            asm volatile("cp.async.cg.shared.global [%0], [%1], 16, %2;"
                         :: "r"(saddr), "l"(gp), "r"(sz) : "memory");
        }
        asm volatile("cp.async.commit_group;" ::: "memory");
    };
    // fp32 ldg+convert staging.
    auto stage_f32 = [&](int tile, __half* buf) {
        int rowBase = tile * MB;
        #pragma unroll
        for (int i = t * 8; i < MB * DIN; i += 256 * 8) {
            int r = i >> 7, c = i & 127;
            int row = rowBase + r;
            uint4 u;
            if (row < n) {
                const float* xp = (const float*)X + (size_t)row * DIN + c;
                float4 v0 = __ldg((const float4*)xp);
                float4 v1 = __ldg((const float4*)(xp + 4));
                half2 h0 = __floats2half2_rn(v0.x, v0.y);
                half2 h1 = __floats2half2_rn(v0.z, v0.w);
                half2 h2 = __floats2half2_rn(v1.x, v1.y);
                half2 h3 = __floats2half2_rn(v1.z, v1.w);
                u = make_uint4(*(uint32_t*)&h0, *(uint32_t*)&h1,
                               *(uint32_t*)&h2, *(uint32_t*)&h3);
            } else u = make_uint4(0u, 0u, 0u, 0u);
            *(uint4*)&buf[r * XS + c] = u;
        }
    };

    uint32_t ws_base = (uint32_t)__cvta_generic_to_shared(Ws);
    uint32_t b_addr = ws_base + (uint32_t)(((wn * 32 + lane) * WKS) * 2);

    int tile = blockIdx.x;
    int cur = 0;
    if (HALF_IN && tile < tiles) stage_async(tile, Xb[0]);

    for (; tile < tiles; tile += gridDim.x) {
        if constexpr (HALF_IN) {
            int nxt = tile + gridDim.x;
            if (nxt < tiles) stage_async(nxt, Xb[cur ^ 1]);
            if (nxt < tiles)
                asm volatile("cp.async.wait_group 1;" ::: "memory");
            else
                asm volatile("cp.async.wait_group 0;" ::: "memory");
            __syncthreads();
        } else {
            __syncthreads();          // previous tile's reads done
            stage_f32(tile, Xb[0]);
            __syncthreads();
        }

        __half* Xs = Xb[cur];
        uint32_t xs_base = (uint32_t)__cvta_generic_to_shared(Xs);
        uint32_t a_addr0 = xs_base + (uint32_t)(((wm * 32 + (lane & 15)) * XS + ((lane >> 4) << 3)) * 2);
        uint32_t a_addr1 = a_addr0 + (uint32_t)(16 * XS * 2);

        float acc[2][4][4];
        #pragma unroll
        for (int a = 0; a < 2; a++)
            #pragma unroll
            for (int u = 0; u < 4; u++)
                #pragma unroll
                for (int k = 0; k < 4; k++) acc[a][u][k] = 0.f;

        #pragma unroll
        for (int ks = 0; ks < DIN / 16; ks++) {
            uint32_t koff = (uint32_t)(ks * 16 * 2);
            uint32_t a[2][4], b0[4], b1[4];
            ldsm_x4(a[0][0], a[0][1], a[0][2], a[0][3], a_addr0 + koff);
            ldsm_x4(a[1][0], a[1][1], a[1][2], a[1][3], a_addr1 + koff);
            ldsm_x4(b0[0], b0[1], b0[2], b0[3], b_addr + koff);
            ldsm_x4(b1[0], b1[1], b1[2], b1[3], b_addr + koff + 16);
            #pragma unroll
            for (int tt = 0; tt < 2; tt++)
                #pragma unroll
                for (int u = 0; u < 4; u++) {
                    asm volatile(
                        "mma.sync.aligned.m16n8k16.row.col.f32.f16.f16.f32 "
                        "{%0,%1,%2,%3}, {%4,%5,%6,%7}, {%8,%9}, {%0,%1,%2,%3};"
                        : "+f"(acc[tt][u][0]), "+f"(acc[tt][u][1]),
                          "+f"(acc[tt][u][2]), "+f"(acc[tt][u][3])
                        : "r"(a[tt][0]), "r"(a[tt][1]), "r"(a[tt][2]), "r"(a[tt][3]),
                          "r"(b0[u]), "r"(b1[u]));
                }
        }

        int rowBase = tile * MB;
        #pragma unroll
        for (int tt = 0; tt < 2; tt++) {
            int r0 = rowBase + wm * 32 + tt * 16 + g;
            int r1 = r0 + 8;
            int cbase = wn * 32 + 2 * tg;
            if (r0 < n) {
                float di = dinv_buf[r0];
                #pragma unroll
                for (int u = 0; u < 4; u++) {
                    half2 h = __floats2half2_rn(acc[tt][u][0] * di, acc[tt][u][1] * di);
                    *(half2*)(G + (size_t)r0 * DOUT + cbase + u * 8) = h;
                }
            }
            if (r1 < n) {
                float di = dinv_buf[r1];
                #pragma unroll
                for (int u = 0; u < 4; u++) {
                    half2 h = __floats2half2_rn(acc[tt][u][2] * di, acc[tt][u][3] * di);
                    *(half2*)(G + (size_t)r1 * DOUT + cbase + u * 8) = h;
                }
            }
        }
        if constexpr (HALF_IN) {
            __syncthreads();          // reads of Xb[cur] done before restage
            cur ^= 1;
        }
    }
}

// ------------------------------ Aggregation --------------------------------

template <int D, bool RELU, typename TOUT>
__global__ __launch_bounds__(256) void k_aggregate(const __half* __restrict__ G,
                                                   const float* __restrict__ bias,
                                                   TOUT* __restrict__ OUT, int n) {
    int wid = (blockIdx.x * blockDim.x + threadIdx.x) >> 5;
    int lane = threadIdx.x & 31;
    if (wid >= n) return;
    constexpr int V = D / 32;

    float acc[V];
    if constexpr (V == 4) {
        uint2 a = *(const uint2*)(G + (size_t)wid * D + lane * 4);
        float2 f0 = __half22float2(*(half2*)&a.x);
        float2 f1 = __half22float2(*(half2*)&a.y);
        acc[0] = f0.x; acc[1] = f0.y; acc[2] = f1.x; acc[3] = f1.y;
    } else {
        uint32_t a = *(const uint32_t*)(G + (size_t)wid * D + lane * 2);
        float2 f = __half22float2(*(half2*)&a);
        acc[0] = f.x; acc[1] = f.y;
    }

    int s0 = rowptr_buf[wid];
    int s1 = rowptr_buf[wid + 1];

    int j = s0;
    for (; j + 3 < s1; j += 4) {
        int sa = __ldg(&csrsrc_buf[j]);
        int sb = __ldg(&csrsrc_buf[j + 1]);
        int sc = __ldg(&csrsrc_buf[j + 2]);
        int sd = __ldg(&csrsrc_buf[j + 3]);
        if constexpr (V == 4) {
            uint2 a = __ldg((const uint2*)(G + (size_t)sa * D) + lane);
            uint2 b = __ldg((const uint2*)(G + (size_t)sb * D) + lane);
            uint2 c = __ldg((const uint2*)(G + (size_t)sc * D) + lane);
            uint2 d = __ldg((const uint2*)(G + (size_t)sd * D) + lane);
            float2 fa0 = __half22float2(*(half2*)&a.x), fa1 = __half22float2(*(half2*)&a.y);
            float2 fb0 = __half22float2(*(half2*)&b.x), fb1 = __half22float2(*(half2*)&b.y);
            float2 fc0 = __half22float2(*(half2*)&c.x), fc1 = __half22float2(*(half2*)&c.y);
            float2 fd0 = __half22float2(*(half2*)&d.x), fd1 = __half22float2(*(half2*)&d.y);
            acc[0] += fa0.x + fb0.x + fc0.x + fd0.x;
            acc[1] += fa0.y + fb0.y + fc0.y + fd0.y;
            acc[2] += fa1.x + fb1.x + fc1.x + fd1.x;
            acc[3] += fa1.y + fb1.y + fc1.y + fd1.y;
        } else {
            uint32_t a = __ldg((const uint32_t*)(G + (size_t)sa * D) + lane);
            uint32_t b = __ldg((const uint32_t*)(G + (size_t)sb * D) + lane);
            uint32_t c = __ldg((const uint32_t*)(G + (size_t)sc * D) + lane);
            uint32_t d = __ldg((const uint32_t*)(G + (size_t)sd * D) + lane);
            float2 fa = __half22float2(*(half2*)&a);
            float2 fb = __half22float2(*(half2*)&b);
            float2 fc = __half22float2(*(half2*)&c);
            float2 fd = __half22float2(*(half2*)&d);
            acc[0] += fa.x + fb.x + fc.x + fd.x;
            acc[1] += fa.y + fb.y + fc.y + fd.y;
        }
    }
    for (; j < s1; j++) {
        int s = __ldg(&csrsrc_buf[j]);
        if constexpr (V == 4) {
            uint2 a = __ldg((const uint2*)(G + (size_t)s * D) + lane);
            float2 f0 = __half22float2(*(half2*)&a.x), f1 = __half22float2(*(half2*)&a.y);
            acc[0] += f0.x; acc[1] += f0.y; acc[2] += f1.x; acc[3] += f1.y;
        } else {
            uint32_t a = __ldg((const uint32_t*)(G + (size_t)s * D) + lane);
            float2 f = __half22float2(*(half2*)&a);
            acc[0] += f.x; acc[1] += f.y;
        }
    }

    float di = dinv_buf[wid];
    if constexpr (V == 4) {
        float4 b = __ldg((const float4*)bias + lane);
        float o0 = acc[0] * di + b.x, o1 = acc[1] * di + b.y;
        float o2 = acc[2] * di + b.z, o3 = acc[3] * di + b.w;
        if (RELU) {
            o0 = fmaxf(o0, 0.f); o1 = fmaxf(o1, 0.f);
            o2 = fmaxf(o2, 0.f); o3 = fmaxf(o3, 0.f);
        }
        if constexpr (sizeof(TOUT) == 2) {
            __half* op = (__half*)OUT + (size_t)wid * D + lane * 4;
            *(half2*)op = __floats2half2_rn(o0, o1);
            *(half2*)(op + 2) = __floats2half2_rn(o2, o3);
        } else {
            float* op = (float*)OUT + (size_t)wid * D + lane * 4;
            *(float4*)op = make_float4(o0, o1, o2, o3);
        }
    } else {
        float2 b = __ldg((const float2*)bias + lane);
        float o0 = acc[0] * di + b.x, o1 = acc[1] * di + b.y;
        if (RELU) { o0 = fmaxf(o0, 0.f); o1 = fmaxf(o1, 0.f); }
        if constexpr (sizeof(TOUT) == 2) {
            __half* op = (__half*)OUT + (size_t)wid * D + lane * 2;
            *(half2*)op = __floats2half2_rn(o0, o1);
        } else {
            float* op = (float*)OUT + (size_t)wid * D + lane * 2;
            *(float2*)op = make_float2(o0, o1);
        }
    }
}

// ------------------------------- launch ------------------------------------

extern "C" void kernel_launch(void* const* d_in, const int* in_sizes, int n_in,
                              void* d_out, int out_size) {
    const float* x  = (const float*)d_in[0];
    const int*   ei = (const int*)d_in[1];
    const float* W1 = (const float*)d_in[2];
    const float* b1 = (const float*)d_in[3];
    const float* W2 = (const float*)d_in[4];
    const float* b2 = (const float*)d_in[5];
    const float* W3 = (const float*)d_in[6];
    const float* b3 = (const float*)d_in[7];

    int n = in_sizes[0] / 128;
    int e = in_sizes[1] / 2;
    const int* src = ei;
    const int* dst = ei + e;

    __half *g, *agg, *wt1, *wt2, *wt3;
    cudaGetSymbolAddress((void**)&g, g_buf);
    cudaGetSymbolAddress((void**)&agg, agg_buf);
    cudaGetSymbolAddress((void**)&wt1, wt1_buf);
    cudaGetSymbolAddress((void**)&wt2, wt2_buf);
    cudaGetSymbolAddress((void**)&wt3, wt3_buf);
    float* out = (float*)d_out;

    int nb = (n + 255) / 256;
    int eb = (e + 255) / 256;
    int scan_blocks = (n + SCAN_B - 1) / SCAN_B;

    // smem: <128,float>: W 128*136 + 1 X buf 64*136      = 52,224 B (3/SM)
    //       <128,half> : W 128*136 + 2 X bufs 64*136     = 69,632 B (3/SM)
    //       <64, half> : W  64*136 + 2 X bufs 128*136    = 87,040 B (2/SM)
    constexpr int SMEM1 = (128 * 136 + 1 * 64 * 136) * 2;
    constexpr int SMEM2 = (128 * 136 + 2 * 64 * 136) * 2;
    constexpr int SMEM3 = (64 * 136 + 2 * 128 * 136) * 2;
    cudaFuncSetAttribute(k_gemm_tc<128, float>,  cudaFuncAttributeMaxDynamicSharedMemorySize, SMEM1);
    cudaFuncSetAttribute(k_gemm_tc<128, __half>, cudaFuncAttributeMaxDynamicSharedMemorySize, SMEM2);
    cudaFuncSetAttribute(k_gemm_tc<64,  __half>, cudaFuncAttributeMaxDynamicSharedMemorySize, SMEM3);

    int tiles128 = (n + 63) / 64;
    int tiles64  = (n + 127) / 128;
    int grid128 = tiles128 < 444 ? tiles128 : 444;
    int grid64  = tiles64  < 296 ? tiles64  : 296;

    // Single stream; GEMM1 is launch #4 (ncu captures launch 4).
    k_prep<<<nb, 256>>>(W1, W2, W3, n);                                     // 1
    k_hist<<<eb, 256>>>(dst, e);                                            // 2
    k_blocksum_dinv<<<scan_blocks, SCAN_B>>>(n);                            // 3
    k_gemm_tc<128, float><<<grid128, 256, SMEM1>>>(x, wt1, g, n, tiles128); // 4
    k_scan_blocksums<<<1, MAX_SCAN_BLOCKS>>>(scan_blocks, n, e);
    k_block_scan<<<scan_blocks, SCAN_B>>>(n);
    k_scatter<<<eb, 256>>>(src, dst, e);

    int agg_blocks = (n * 32 + 255) / 256;

    k_aggregate<128, true, __half><<<agg_blocks, 256>>>(g, b1, agg, n);

    k_gemm_tc<128, __half><<<grid128, 256, SMEM2>>>(agg, wt2, g, n, tiles128);
    k_aggregate<128, true, __half><<<agg_blocks, 256>>>(g, b2, agg, n);

    k_gemm_tc<64, __half><<<grid64, 256, SMEM3>>>(agg, wt3, g, n, tiles64);
    k_aggregate<64, false, float><<<agg_blocks, 256>>>(g, b3, out, n);
}

// round 11
// speedup vs baseline: 1.1327x; 1.0451x over previous
#include <cuda_runtime.h>
#include <cuda_fp16.h>
#include <cstddef>
#include <cstdint>

// ---------------------------------------------------------------------------
// GCN 3-layer encoder, fp16 pipeline, single-stream schedule.
//   per layer: g = (act(in) @ W) * dinv[row]   (fp16 MMA, fp32 accum)
//              out_i = dinv_i * (sum_{e: dst=i} g[src_e] + g_i) + b  [+ReLU]
// Persistent-block GEMMs. Aggregation sums 4-edge groups in fp16 (HADD2),
// folds into fp32 accumulators (2.3x fewer ALU ops per edge).
// ---------------------------------------------------------------------------

#define N_MAX 100000
#define E_MAX 1600000
#define SCAN_B 1024
#define MAX_SCAN_BLOCKS 128

__device__ __half g_buf[(size_t)N_MAX * 128];
__device__ __half agg_buf[(size_t)N_MAX * 128];
__device__ float dinv_buf[N_MAX];
__device__ int   deg_buf[N_MAX];
__device__ int   rowptr_buf[N_MAX + 1];
__device__ int   cursor_buf[N_MAX];
__device__ int   csrsrc_buf[E_MAX];
__device__ int   blocksum_buf[MAX_SCAN_BLOCKS];
__device__ __half wt1_buf[128 * 128];
__device__ __half wt2_buf[128 * 128];
__device__ __half wt3_buf[64 * 128];

// ---------------- prep: zero deg + W transposes -----------------------------

__global__ void k_prep(const float* __restrict__ W1, const float* __restrict__ W2,
                       const float* __restrict__ W3, int n) {
    int i = blockIdx.x * blockDim.x + threadIdx.x;
    if (i < n) deg_buf[i] = 0;
    if (i < 128 * 128) {
        int k = i >> 7, c = i & 127;
        wt1_buf[c * 128 + k] = __float2half_rn(__ldg(&W1[i]));
        wt2_buf[c * 128 + k] = __float2half_rn(__ldg(&W2[i]));
    }
    if (i < 128 * 64) {
        int k = i >> 6, c = i & 63;
        wt3_buf[c * 128 + k] = __float2half_rn(__ldg(&W3[i]));
    }
}

// -------------------------------- CSR prep --------------------------------

__global__ void k_hist(const int* __restrict__ dst, int e) {
    int i = blockIdx.x * blockDim.x + threadIdx.x;
    if (i < e) atomicAdd(&deg_buf[dst[i]], 1);
}

__global__ __launch_bounds__(SCAN_B) void k_blocksum_dinv(int n) {
    __shared__ int wsum[32];
    int i = blockIdx.x * SCAN_B + threadIdx.x;
    int v = 0;
    if (i < n) {
        v = deg_buf[i];
        dinv_buf[i] = rsqrtf((float)v + 1.0f);
    }
    int s = v;
    #pragma unroll
    for (int off = 16; off > 0; off >>= 1)
        s += __shfl_down_sync(0xffffffffu, s, off);
    int lane = threadIdx.x & 31, w = threadIdx.x >> 5;
    if (lane == 0) wsum[w] = s;
    __syncthreads();
    if (w == 0) {
        int t = wsum[lane];
        #pragma unroll
        for (int off = 16; off > 0; off >>= 1)
            t += __shfl_down_sync(0xffffffffu, t, off);
        if (lane == 0) blocksum_buf[blockIdx.x] = t;
    }
}

__global__ void k_scan_blocksums(int nblocks, int n, int e) {
    __shared__ int wsum[4];
    int t = threadIdx.x;
    int v = (t < nblocks) ? blocksum_buf[t] : 0;
    int lane = t & 31, w = t >> 5;
    int s = v;
    #pragma unroll
    for (int off = 1; off < 32; off <<= 1) {
        int x = __shfl_up_sync(0xffffffffu, s, off);
        if (lane >= off) s += x;
    }
    if (lane == 31) wsum[w] = s;
    __syncthreads();
    int base = 0;
    #pragma unroll
    for (int k = 0; k < 4; k++) base += (k < w) ? wsum[k] : 0;
    if (t < nblocks) blocksum_buf[t] = base + s - v;
    if (t == 0) rowptr_buf[n] = e;
}

__global__ __launch_bounds__(SCAN_B) void k_block_scan(int n) {
    __shared__ int wsum[32];
    int i = blockIdx.x * SCAN_B + threadIdx.x;
    int v = (i < n) ? deg_buf[i] : 0;
    int lane = threadIdx.x & 31, w = threadIdx.x >> 5;
    int s = v;
    #pragma unroll
    for (int off = 1; off < 32; off <<= 1) {
        int x = __shfl_up_sync(0xffffffffu, s, off);
        if (lane >= off) s += x;
    }
    if (lane == 31) wsum[w] = s;
    __syncthreads();
    if (w == 0) {
        int ws = wsum[lane];
        #pragma unroll
        for (int off = 1; off < 32; off <<= 1) {
            int x = __shfl_up_sync(0xffffffffu, ws, off);
            if (lane >= off) ws += x;
        }
        wsum[lane] = ws;
    }
    __syncthreads();
    int warpBase = (w > 0) ? wsum[w - 1] : 0;
    if (i < n) {
        int p = blocksum_buf[blockIdx.x] + warpBase + (s - v);
        rowptr_buf[i] = p;
        cursor_buf[i] = p;
    }
}

__global__ void k_scatter(const int* __restrict__ src, const int* __restrict__ dst, int e) {
    int i = blockIdx.x * blockDim.x + threadIdx.x;
    if (i < e) {
        int d = dst[i];
        int pos = atomicAdd(&cursor_buf[d], 1);
        csrsrc_buf[pos] = src[i];
    }
}

// ----------------------- fp16 tensor-core GEMM -----------------------------

__device__ __forceinline__ void ldsm_x4(uint32_t& r0, uint32_t& r1,
                                        uint32_t& r2, uint32_t& r3, uint32_t addr) {
    asm volatile("ldmatrix.sync.aligned.m8n8.x4.shared.b16 {%0,%1,%2,%3}, [%4];"
                 : "=r"(r0), "=r"(r1), "=r"(r2), "=r"(r3) : "r"(addr));
}

template <int DOUT, typename TIN>
__global__ __launch_bounds__(256) void k_gemm_tc(const TIN* __restrict__ X,
                                                 const __half* __restrict__ Wt,
                                                 __half* __restrict__ G,
                                                 int n, int tiles) {
    constexpr bool HALF_IN = (sizeof(TIN) == 2);
    constexpr int DIN = 128;
    constexpr int WN = DOUT / 32;
    constexpr int WM = 8 / WN;
    constexpr int MB = WM * 32;
    constexpr int XS = 136;
    constexpr int WKS = 136;
    constexpr int XTILE = MB * XS;
    constexpr int NBUF = HALF_IN ? 2 : 1;

    extern __shared__ __half hsm[];
    __half* Ws = hsm;
    __half* Xb[2] = { hsm + DOUT * WKS,
                      hsm + DOUT * WKS + (NBUF == 2 ? XTILE : 0) };

    int t = threadIdx.x;
    int warp = t >> 5, lane = t & 31;
    int wm = warp / WN, wn = warp % WN;
    int g = lane >> 2, tg = lane & 3;

    #pragma unroll
    for (int i = t * 8; i < DOUT * DIN; i += 256 * 8) {
        int c = i >> 7, k = i & 127;
        uint4 v = __ldg((const uint4*)(Wt + i));
        *(uint4*)&Ws[c * WKS + k] = v;
    }

    auto stage_async = [&](int tile, __half* buf) {
        int rowBase = tile * MB;
        #pragma unroll
        for (int i = t * 8; i < MB * DIN; i += 256 * 8) {
            int r = i >> 7, c = i & 127;
            int row = rowBase + r;
            uint32_t saddr = (uint32_t)__cvta_generic_to_shared(&buf[r * XS + c]);
            const __half* gp = (const __half*)X + (size_t)(row < n ? row : 0) * DIN + c;
            int sz = (row < n) ? 16 : 0;
            asm volatile("cp.async.cg.shared.global [%0], [%1], 16, %2;"
                         :: "r"(saddr), "l"(gp), "r"(sz) : "memory");
        }
        asm volatile("cp.async.commit_group;" ::: "memory");
    };
    auto stage_f32 = [&](int tile, __half* buf) {
        int rowBase = tile * MB;
        #pragma unroll
        for (int i = t * 8; i < MB * DIN; i += 256 * 8) {
            int r = i >> 7, c = i & 127;
            int row = rowBase + r;
            uint4 u;
            if (row < n) {
                const float* xp = (const float*)X + (size_t)row * DIN + c;
                float4 v0 = __ldg((const float4*)xp);
                float4 v1 = __ldg((const float4*)(xp + 4));
                half2 h0 = __floats2half2_rn(v0.x, v0.y);
                half2 h1 = __floats2half2_rn(v0.z, v0.w);
                half2 h2 = __floats2half2_rn(v1.x, v1.y);
                half2 h3 = __floats2half2_rn(v1.z, v1.w);
                u = make_uint4(*(uint32_t*)&h0, *(uint32_t*)&h1,
                               *(uint32_t*)&h2, *(uint32_t*)&h3);
            } else u = make_uint4(0u, 0u, 0u, 0u);
            *(uint4*)&buf[r * XS + c] = u;
        }
    };

    uint32_t ws_base = (uint32_t)__cvta_generic_to_shared(Ws);
    uint32_t b_addr = ws_base + (uint32_t)(((wn * 32 + lane) * WKS) * 2);

    int tile = blockIdx.x;
    int cur = 0;
    if (HALF_IN && tile < tiles) stage_async(tile, Xb[0]);

    for (; tile < tiles; tile += gridDim.x) {
        if constexpr (HALF_IN) {
            int nxt = tile + gridDim.x;
            if (nxt < tiles) stage_async(nxt, Xb[cur ^ 1]);
            if (nxt < tiles)
                asm volatile("cp.async.wait_group 1;" ::: "memory");
            else
                asm volatile("cp.async.wait_group 0;" ::: "memory");
            __syncthreads();
        } else {
            __syncthreads();
            stage_f32(tile, Xb[0]);
            __syncthreads();
        }

        __half* Xs = Xb[cur];
        uint32_t xs_base = (uint32_t)__cvta_generic_to_shared(Xs);
        uint32_t a_addr0 = xs_base + (uint32_t)(((wm * 32 + (lane & 15)) * XS + ((lane >> 4) << 3)) * 2);
        uint32_t a_addr1 = a_addr0 + (uint32_t)(16 * XS * 2);

        float acc[2][4][4];
        #pragma unroll
        for (int a = 0; a < 2; a++)
            #pragma unroll
            for (int u = 0; u < 4; u++)
                #pragma unroll
                for (int k = 0; k < 4; k++) acc[a][u][k] = 0.f;

        #pragma unroll
        for (int ks = 0; ks < DIN / 16; ks++) {
            uint32_t koff = (uint32_t)(ks * 16 * 2);
            uint32_t a[2][4], b0[4], b1[4];
            ldsm_x4(a[0][0], a[0][1], a[0][2], a[0][3], a_addr0 + koff);
            ldsm_x4(a[1][0], a[1][1], a[1][2], a[1][3], a_addr1 + koff);
            ldsm_x4(b0[0], b0[1], b0[2], b0[3], b_addr + koff);
            ldsm_x4(b1[0], b1[1], b1[2], b1[3], b_addr + koff + 16);
            #pragma unroll
            for (int tt = 0; tt < 2; tt++)
                #pragma unroll
                for (int u = 0; u < 4; u++) {
                    asm volatile(
                        "mma.sync.aligned.m16n8k16.row.col.f32.f16.f16.f32 "
                        "{%0,%1,%2,%3}, {%4,%5,%6,%7}, {%8,%9}, {%0,%1,%2,%3};"
                        : "+f"(acc[tt][u][0]), "+f"(acc[tt][u][1]),
                          "+f"(acc[tt][u][2]), "+f"(acc[tt][u][3])
                        : "r"(a[tt][0]), "r"(a[tt][1]), "r"(a[tt][2]), "r"(a[tt][3]),
                          "r"(b0[u]), "r"(b1[u]));
                }
        }

        int rowBase = tile * MB;
        #pragma unroll
        for (int tt = 0; tt < 2; tt++) {
            int r0 = rowBase + wm * 32 + tt * 16 + g;
            int r1 = r0 + 8;
            int cbase = wn * 32 + 2 * tg;
            if (r0 < n) {
                float di = dinv_buf[r0];
                #pragma unroll
                for (int u = 0; u < 4; u++) {
                    half2 h = __floats2half2_rn(acc[tt][u][0] * di, acc[tt][u][1] * di);
                    *(half2*)(G + (size_t)r0 * DOUT + cbase + u * 8) = h;
                }
            }
            if (r1 < n) {
                float di = dinv_buf[r1];
                #pragma unroll
                for (int u = 0; u < 4; u++) {
                    half2 h = __floats2half2_rn(acc[tt][u][2] * di, acc[tt][u][3] * di);
                    *(half2*)(G + (size_t)r1 * DOUT + cbase + u * 8) = h;
                }
            }
        }
        if constexpr (HALF_IN) {
            __syncthreads();
            cur ^= 1;
        }
    }
}

// ------------------------------ Aggregation --------------------------------
// Unroll-4 body sums the 4 gathered rows in fp16 (HADD2 tree), then folds the
// partial into fp32 accumulators: ~2.3x fewer ALU ops per edge.

template <int D, bool RELU, typename TOUT>
__global__ __launch_bounds__(256) void k_aggregate(const __half* __restrict__ G,
                                                   const float* __restrict__ bias,
                                                   TOUT* __restrict__ OUT, int n) {
    int wid = (blockIdx.x * blockDim.x + threadIdx.x) >> 5;
    int lane = threadIdx.x & 31;
    if (wid >= n) return;
    constexpr int V = D / 32;

    float acc[V];
    if constexpr (V == 4) {
        uint2 a = *(const uint2*)(G + (size_t)wid * D + lane * 4);
        float2 f0 = __half22float2(*(half2*)&a.x);
        float2 f1 = __half22float2(*(half2*)&a.y);
        acc[0] = f0.x; acc[1] = f0.y; acc[2] = f1.x; acc[3] = f1.y;
    } else {
        uint32_t a = *(const uint32_t*)(G + (size_t)wid * D + lane * 2);
        float2 f = __half22float2(*(half2*)&a);
        acc[0] = f.x; acc[1] = f.y;
    }

    int s0 = rowptr_buf[wid];
    int s1 = rowptr_buf[wid + 1];

    int j = s0;
    for (; j + 3 < s1; j += 4) {
        int sa = __ldg(&csrsrc_buf[j]);
        int sb = __ldg(&csrsrc_buf[j + 1]);
        int sc = __ldg(&csrsrc_buf[j + 2]);
        int sd = __ldg(&csrsrc_buf[j + 3]);
        if constexpr (V == 4) {
            uint2 a = __ldg((const uint2*)(G + (size_t)sa * D) + lane);
            uint2 b = __ldg((const uint2*)(G + (size_t)sb * D) + lane);
            uint2 c = __ldg((const uint2*)(G + (size_t)sc * D) + lane);
            uint2 d = __ldg((const uint2*)(G + (size_t)sd * D) + lane);
            half2 sx = __hadd2(__hadd2(*(half2*)&a.x, *(half2*)&b.x),
                               __hadd2(*(half2*)&c.x, *(half2*)&d.x));
            half2 sy = __hadd2(__hadd2(*(half2*)&a.y, *(half2*)&b.y),
                               __hadd2(*(half2*)&c.y, *(half2*)&d.y));
            float2 fx = __half22float2(sx);
            float2 fy = __half22float2(sy);
            acc[0] += fx.x; acc[1] += fx.y; acc[2] += fy.x; acc[3] += fy.y;
        } else {
            uint32_t a = __ldg((const uint32_t*)(G + (size_t)sa * D) + lane);
            uint32_t b = __ldg((const uint32_t*)(G + (size_t)sb * D) + lane);
            uint32_t c = __ldg((const uint32_t*)(G + (size_t)sc * D) + lane);
            uint32_t d = __ldg((const uint32_t*)(G + (size_t)sd * D) + lane);
            half2 sx = __hadd2(__hadd2(*(half2*)&a, *(half2*)&b),
                               __hadd2(*(half2*)&c, *(half2*)&d));
            float2 fx = __half22float2(sx);
            acc[0] += fx.x; acc[1] += fx.y;
        }
    }
    for (; j < s1; j++) {
        int s = __ldg(&csrsrc_buf[j]);
        if constexpr (V == 4) {
            uint2 a = __ldg((const uint2*)(G + (size_t)s * D) + lane);
            float2 f0 = __half22float2(*(half2*)&a.x), f1 = __half22float2(*(half2*)&a.y);
            acc[0] += f0.x; acc[1] += f0.y; acc[2] += f1.x; acc[3] += f1.y;
        } else {
            uint32_t a = __ldg((const uint32_t*)(G + (size_t)s * D) + lane);
            float2 f = __half22float2(*(half2*)&a);
            acc[0] += f.x; acc[1] += f.y;
        }
    }

    float di = dinv_buf[wid];
    if constexpr (V == 4) {
        float4 b = __ldg((const float4*)bias + lane);
        float o0 = acc[0] * di + b.x, o1 = acc[1] * di + b.y;
        float o2 = acc[2] * di + b.z, o3 = acc[3] * di + b.w;
        if (RELU) {
            o0 = fmaxf(o0, 0.f); o1 = fmaxf(o1, 0.f);
            o2 = fmaxf(o2, 0.f); o3 = fmaxf(o3, 0.f);
        }
        if constexpr (sizeof(TOUT) == 2) {
            __half* op = (__half*)OUT + (size_t)wid * D + lane * 4;
            *(half2*)op = __floats2half2_rn(o0, o1);
            *(half2*)(op + 2) = __floats2half2_rn(o2, o3);
        } else {
            float* op = (float*)OUT + (size_t)wid * D + lane * 4;
            *(float4*)op = make_float4(o0, o1, o2, o3);
        }
    } else {
        float2 b = __ldg((const float2*)bias + lane);
        float o0 = acc[0] * di + b.x, o1 = acc[1] * di + b.y;
        if (RELU) { o0 = fmaxf(o0, 0.f); o1 = fmaxf(o1, 0.f); }
        if constexpr (sizeof(TOUT) == 2) {
            __half* op = (__half*)OUT + (size_t)wid * D + lane * 2;
            *(half2*)op = __floats2half2_rn(o0, o1);
        } else {
            float* op = (float*)OUT + (size_t)wid * D + lane * 2;
            *(float2*)op = make_float2(o0, o1);
        }
    }
}

// ------------------------------- launch ------------------------------------

extern "C" void kernel_launch(void* const* d_in, const int* in_sizes, int n_in,
                              void* d_out, int out_size) {
    const float* x  = (const float*)d_in[0];
    const int*   ei = (const int*)d_in[1];
    const float* W1 = (const float*)d_in[2];
    const float* b1 = (const float*)d_in[3];
    const float* W2 = (const float*)d_in[4];
    const float* b2 = (const float*)d_in[5];
    const float* W3 = (const float*)d_in[6];
    const float* b3 = (const float*)d_in[7];

    int n = in_sizes[0] / 128;
    int e = in_sizes[1] / 2;
    const int* src = ei;
    const int* dst = ei + e;

    __half *g, *agg, *wt1, *wt2, *wt3;
    cudaGetSymbolAddress((void**)&g, g_buf);
    cudaGetSymbolAddress((void**)&agg, agg_buf);
    cudaGetSymbolAddress((void**)&wt1, wt1_buf);
    cudaGetSymbolAddress((void**)&wt2, wt2_buf);
    cudaGetSymbolAddress((void**)&wt3, wt3_buf);
    float* out = (float*)d_out;

    int nb = (n + 255) / 256;
    int eb = (e + 255) / 256;
    int scan_blocks = (n + SCAN_B - 1) / SCAN_B;

    constexpr int SMEM1 = (128 * 136 + 1 * 64 * 136) * 2;
    constexpr int SMEM2 = (128 * 136 + 2 * 64 * 136) * 2;
    constexpr int SMEM3 = (64 * 136 + 2 * 128 * 136) * 2;
    cudaFuncSetAttribute(k_gemm_tc<128, float>,  cudaFuncAttributeMaxDynamicSharedMemorySize, SMEM1);
    cudaFuncSetAttribute(k_gemm_tc<128, __half>, cudaFuncAttributeMaxDynamicSharedMemorySize, SMEM2);
    cudaFuncSetAttribute(k_gemm_tc<64,  __half>, cudaFuncAttributeMaxDynamicSharedMemorySize, SMEM3);

    int tiles128 = (n + 63) / 64;
    int tiles64  = (n + 127) / 128;
    int grid128 = tiles128 < 444 ? tiles128 : 444;
    int grid64  = tiles64  < 296 ? tiles64  : 296;

    // Single stream; GEMM1 is launch #4 (ncu captures launch 4).
    k_prep<<<nb, 256>>>(W1, W2, W3, n);                                     // 1
    k_hist<<<eb, 256>>>(dst, e);                                            // 2
    k_blocksum_dinv<<<scan_blocks, SCAN_B>>>(n);                            // 3
    k_gemm_tc<128, float><<<grid128, 256, SMEM1>>>(x, wt1, g, n, tiles128); // 4
    k_scan_blocksums<<<1, MAX_SCAN_BLOCKS>>>(scan_blocks, n, e);
    k_block_scan<<<scan_blocks, SCAN_B>>>(n);
    k_scatter<<<eb, 256>>>(src, dst, e);

    int agg_blocks = (n * 32 + 255) / 256;

    k_aggregate<128, true, __half><<<agg_blocks, 256>>>(g, b1, agg, n);

    k_gemm_tc<128, __half><<<grid128, 256, SMEM2>>>(agg, wt2, g, n, tiles128);
    k_aggregate<128, true, __half><<<agg_blocks, 256>>>(g, b2, agg, n);

    k_gemm_tc<64, __half><<<grid64, 256, SMEM3>>>(agg, wt3, g, n, tiles64);
    k_aggregate<64, false, float><<<agg_blocks, 256>>>(g, b3, out, n);
}

// round 12
// speedup vs baseline: 1.1419x; 1.0082x over previous
#include <cuda_runtime.h>
#include <cuda_fp16.h>
#include <cstddef>
#include <cstdint>

// ---------------------------------------------------------------------------
// GCN 3-layer encoder, fp16 pipeline, single-stream schedule.
//   per layer: g = (act(in) @ W) * dinv[row]   (fp16 MMA, fp32 accum)
//              out_i = dinv_i * (sum_{e: dst=i} g[src_e] + g_i) + b  [+ReLU]
// Persistent-block GEMMs. Aggregation: unroll-8 gathers (MLP=8) with two
// 4-row fp16 HADD2 trees folded into fp32 accumulators.
// ---------------------------------------------------------------------------

#define N_MAX 100000
#define E_MAX 1600000
#define SCAN_B 1024
#define MAX_SCAN_BLOCKS 128

__device__ __half g_buf[(size_t)N_MAX * 128];
__device__ __half agg_buf[(size_t)N_MAX * 128];
__device__ float dinv_buf[N_MAX];
__device__ int   deg_buf[N_MAX];
__device__ int   rowptr_buf[N_MAX + 1];
__device__ int   cursor_buf[N_MAX];
__device__ int   csrsrc_buf[E_MAX];
__device__ int   blocksum_buf[MAX_SCAN_BLOCKS];
__device__ __half wt1_buf[128 * 128];
__device__ __half wt2_buf[128 * 128];
__device__ __half wt3_buf[64 * 128];

// ---------------- prep: zero deg + W transposes -----------------------------

__global__ void k_prep(const float* __restrict__ W1, const float* __restrict__ W2,
                       const float* __restrict__ W3, int n) {
    int i = blockIdx.x * blockDim.x + threadIdx.x;
    if (i < n) deg_buf[i] = 0;
    if (i < 128 * 128) {
        int k = i >> 7, c = i & 127;
        wt1_buf[c * 128 + k] = __float2half_rn(__ldg(&W1[i]));
        wt2_buf[c * 128 + k] = __float2half_rn(__ldg(&W2[i]));
    }
    if (i < 128 * 64) {
        int k = i >> 6, c = i & 63;
        wt3_buf[c * 128 + k] = __float2half_rn(__ldg(&W3[i]));
    }
}

// -------------------------------- CSR prep --------------------------------

__global__ void k_hist(const int* __restrict__ dst, int e) {
    int i = blockIdx.x * blockDim.x + threadIdx.x;
    if (i < e) atomicAdd(&deg_buf[dst[i]], 1);
}

__global__ __launch_bounds__(SCAN_B) void k_blocksum_dinv(int n) {
    __shared__ int wsum[32];
    int i = blockIdx.x * SCAN_B + threadIdx.x;
    int v = 0;
    if (i < n) {
        v = deg_buf[i];
        dinv_buf[i] = rsqrtf((float)v + 1.0f);
    }
    int s = v;
    #pragma unroll
    for (int off = 16; off > 0; off >>= 1)
        s += __shfl_down_sync(0xffffffffu, s, off);
    int lane = threadIdx.x & 31, w = threadIdx.x >> 5;
    if (lane == 0) wsum[w] = s;
    __syncthreads();
    if (w == 0) {
        int t = wsum[lane];
        #pragma unroll
        for (int off = 16; off > 0; off >>= 1)
            t += __shfl_down_sync(0xffffffffu, t, off);
        if (lane == 0) blocksum_buf[blockIdx.x] = t;
    }
}

__global__ void k_scan_blocksums(int nblocks, int n, int e) {
    __shared__ int wsum[4];
    int t = threadIdx.x;
    int v = (t < nblocks) ? blocksum_buf[t] : 0;
    int lane = t & 31, w = t >> 5;
    int s = v;
    #pragma unroll
    for (int off = 1; off < 32; off <<= 1) {
        int x = __shfl_up_sync(0xffffffffu, s, off);
        if (lane >= off) s += x;
    }
    if (lane == 31) wsum[w] = s;
    __syncthreads();
    int base = 0;
    #pragma unroll
    for (int k = 0; k < 4; k++) base += (k < w) ? wsum[k] : 0;
    if (t < nblocks) blocksum_buf[t] = base + s - v;
    if (t == 0) rowptr_buf[n] = e;
}

__global__ __launch_bounds__(SCAN_B) void k_block_scan(int n) {
    __shared__ int wsum[32];
    int i = blockIdx.x * SCAN_B + threadIdx.x;
    int v = (i < n) ? deg_buf[i] : 0;
    int lane = threadIdx.x & 31, w = threadIdx.x >> 5;
    int s = v;
    #pragma unroll
    for (int off = 1; off < 32; off <<= 1) {
        int x = __shfl_up_sync(0xffffffffu, s, off);
        if (lane >= off) s += x;
    }
    if (lane == 31) wsum[w] = s;
    __syncthreads();
    if (w == 0) {
        int ws = wsum[lane];
        #pragma unroll
        for (int off = 1; off < 32; off <<= 1) {
            int x = __shfl_up_sync(0xffffffffu, ws, off);
            if (lane >= off) ws += x;
        }
        wsum[lane] = ws;
    }
    __syncthreads();
    int warpBase = (w > 0) ? wsum[w - 1] : 0;
    if (i < n) {
        int p = blocksum_buf[blockIdx.x] + warpBase + (s - v);
        rowptr_buf[i] = p;
        cursor_buf[i] = p;
    }
}

__global__ void k_scatter(const int* __restrict__ src, const int* __restrict__ dst, int e) {
    int i = blockIdx.x * blockDim.x + threadIdx.x;
    if (i < e) {
        int d = dst[i];
        int pos = atomicAdd(&cursor_buf[d], 1);
        csrsrc_buf[pos] = src[i];
    }
}

// ----------------------- fp16 tensor-core GEMM -----------------------------

__device__ __forceinline__ void ldsm_x4(uint32_t& r0, uint32_t& r1,
                                        uint32_t& r2, uint32_t& r3, uint32_t addr) {
    asm volatile("ldmatrix.sync.aligned.m8n8.x4.shared.b16 {%0,%1,%2,%3}, [%4];"
                 : "=r"(r0), "=r"(r1), "=r"(r2), "=r"(r3) : "r"(addr));
}

template <int DOUT, typename TIN>
__global__ __launch_bounds__(256) void k_gemm_tc(const TIN* __restrict__ X,
                                                 const __half* __restrict__ Wt,
                                                 __half* __restrict__ G,
                                                 int n, int tiles) {
    constexpr bool HALF_IN = (sizeof(TIN) == 2);
    constexpr int DIN = 128;
    constexpr int WN = DOUT / 32;
    constexpr int WM = 8 / WN;
    constexpr int MB = WM * 32;
    constexpr int XS = 136;
    constexpr int WKS = 136;
    constexpr int XTILE = MB * XS;
    constexpr int NBUF = HALF_IN ? 2 : 1;

    extern __shared__ __half hsm[];
    __half* Ws = hsm;
    __half* Xb[2] = { hsm + DOUT * WKS,
                      hsm + DOUT * WKS + (NBUF == 2 ? XTILE : 0) };

    int t = threadIdx.x;
    int warp = t >> 5, lane = t & 31;
    int wm = warp / WN, wn = warp % WN;
    int g = lane >> 2, tg = lane & 3;

    #pragma unroll
    for (int i = t * 8; i < DOUT * DIN; i += 256 * 8) {
        int c = i >> 7, k = i & 127;
        uint4 v = __ldg((const uint4*)(Wt + i));
        *(uint4*)&Ws[c * WKS + k] = v;
    }

    auto stage_async = [&](int tile, __half* buf) {
        int rowBase = tile * MB;
        #pragma unroll
        for (int i = t * 8; i < MB * DIN; i += 256 * 8) {
            int r = i >> 7, c = i & 127;
            int row = rowBase + r;
            uint32_t saddr = (uint32_t)__cvta_generic_to_shared(&buf[r * XS + c]);
            const __half* gp = (const __half*)X + (size_t)(row < n ? row : 0) * DIN + c;
            int sz = (row < n) ? 16 : 0;
            asm volatile("cp.async.cg.shared.global [%0], [%1], 16, %2;"
                         :: "r"(saddr), "l"(gp), "r"(sz) : "memory");
        }
        asm volatile("cp.async.commit_group;" ::: "memory");
    };
    auto stage_f32 = [&](int tile, __half* buf) {
        int rowBase = tile * MB;
        #pragma unroll
        for (int i = t * 8; i < MB * DIN; i += 256 * 8) {
            int r = i >> 7, c = i & 127;
            int row = rowBase + r;
            uint4 u;
            if (row < n) {
                const float* xp = (const float*)X + (size_t)row * DIN + c;
                float4 v0 = __ldg((const float4*)xp);
                float4 v1 = __ldg((const float4*)(xp + 4));
                half2 h0 = __floats2half2_rn(v0.x, v0.y);
                half2 h1 = __floats2half2_rn(v0.z, v0.w);
                half2 h2 = __floats2half2_rn(v1.x, v1.y);
                half2 h3 = __floats2half2_rn(v1.z, v1.w);
                u = make_uint4(*(uint32_t*)&h0, *(uint32_t*)&h1,
                               *(uint32_t*)&h2, *(uint32_t*)&h3);
            } else u = make_uint4(0u, 0u, 0u, 0u);
            *(uint4*)&buf[r * XS + c] = u;
        }
    };

    uint32_t ws_base = (uint32_t)__cvta_generic_to_shared(Ws);
    uint32_t b_addr = ws_base + (uint32_t)(((wn * 32 + lane) * WKS) * 2);

    int tile = blockIdx.x;
    int cur = 0;
    if (HALF_IN && tile < tiles) stage_async(tile, Xb[0]);

    for (; tile < tiles; tile += gridDim.x) {
        if constexpr (HALF_IN) {
            int nxt = tile + gridDim.x;
            if (nxt < tiles) stage_async(nxt, Xb[cur ^ 1]);
            if (nxt < tiles)
                asm volatile("cp.async.wait_group 1;" ::: "memory");
            else
                asm volatile("cp.async.wait_group 0;" ::: "memory");
            __syncthreads();
        } else {
            __syncthreads();
            stage_f32(tile, Xb[0]);
            __syncthreads();
        }

        __half* Xs = Xb[cur];
        uint32_t xs_base = (uint32_t)__cvta_generic_to_shared(Xs);
        uint32_t a_addr0 = xs_base + (uint32_t)(((wm * 32 + (lane & 15)) * XS + ((lane >> 4) << 3)) * 2);
        uint32_t a_addr1 = a_addr0 + (uint32_t)(16 * XS * 2);

        float acc[2][4][4];
        #pragma unroll
        for (int a = 0; a < 2; a++)
            #pragma unroll
            for (int u = 0; u < 4; u++)
                #pragma unroll
                for (int k = 0; k < 4; k++) acc[a][u][k] = 0.f;

        #pragma unroll
        for (int ks = 0; ks < DIN / 16; ks++) {
            uint32_t koff = (uint32_t)(ks * 16 * 2);
            uint32_t a[2][4], b0[4], b1[4];
            ldsm_x4(a[0][0], a[0][1], a[0][2], a[0][3], a_addr0 + koff);
            ldsm_x4(a[1][0], a[1][1], a[1][2], a[1][3], a_addr1 + koff);
            ldsm_x4(b0[0], b0[1], b0[2], b0[3], b_addr + koff);
            ldsm_x4(b1[0], b1[1], b1[2], b1[3], b_addr + koff + 16);
            #pragma unroll
            for (int tt = 0; tt < 2; tt++)
                #pragma unroll
                for (int u = 0; u < 4; u++) {
                    asm volatile(
                        "mma.sync.aligned.m16n8k16.row.col.f32.f16.f16.f32 "
                        "{%0,%1,%2,%3}, {%4,%5,%6,%7}, {%8,%9}, {%0,%1,%2,%3};"
                        : "+f"(acc[tt][u][0]), "+f"(acc[tt][u][1]),
                          "+f"(acc[tt][u][2]), "+f"(acc[tt][u][3])
                        : "r"(a[tt][0]), "r"(a[tt][1]), "r"(a[tt][2]), "r"(a[tt][3]),
                          "r"(b0[u]), "r"(b1[u]));
                }
        }

        int rowBase = tile * MB;
        #pragma unroll
        for (int tt = 0; tt < 2; tt++) {
            int r0 = rowBase + wm * 32 + tt * 16 + g;
            int r1 = r0 + 8;
            int cbase = wn * 32 + 2 * tg;
            if (r0 < n) {
                float di = dinv_buf[r0];
                #pragma unroll
                for (int u = 0; u < 4; u++) {
                    half2 h = __floats2half2_rn(acc[tt][u][0] * di, acc[tt][u][1] * di);
                    *(half2*)(G + (size_t)r0 * DOUT + cbase + u * 8) = h;
                }
            }
            if (r1 < n) {
                float di = dinv_buf[r1];
                #pragma unroll
                for (int u = 0; u < 4; u++) {
                    half2 h = __floats2half2_rn(acc[tt][u][2] * di, acc[tt][u][3] * di);
                    *(half2*)(G + (size_t)r1 * DOUT + cbase + u * 8) = h;
                }
            }
        }
        if constexpr (HALF_IN) {
            __syncthreads();
            cur ^= 1;
        }
    }
}

// ------------------------------ Aggregation --------------------------------
// Unroll-8 gathers (MLP=8); two 4-row fp16 HADD2 trees per group, folded into
// fp32 accumulators (fp16 partial depth unchanged vs unroll-4 version).

template <int D, bool RELU, typename TOUT>
__global__ __launch_bounds__(256) void k_aggregate(const __half* __restrict__ G,
                                                   const float* __restrict__ bias,
                                                   TOUT* __restrict__ OUT, int n) {
    int wid = (blockIdx.x * blockDim.x + threadIdx.x) >> 5;
    int lane = threadIdx.x & 31;
    if (wid >= n) return;
    constexpr int V = D / 32;

    float acc[V];
    if constexpr (V == 4) {
        uint2 a = *(const uint2*)(G + (size_t)wid * D + lane * 4);
        float2 f0 = __half22float2(*(half2*)&a.x);
        float2 f1 = __half22float2(*(half2*)&a.y);
        acc[0] = f0.x; acc[1] = f0.y; acc[2] = f1.x; acc[3] = f1.y;
    } else {
        uint32_t a = *(const uint32_t*)(G + (size_t)wid * D + lane * 2);
        float2 f = __half22float2(*(half2*)&a);
        acc[0] = f.x; acc[1] = f.y;
    }

    int s0 = rowptr_buf[wid];
    int s1 = rowptr_buf[wid + 1];

    int j = s0;
    for (; j + 7 < s1; j += 8) {
        int si[8];
        #pragma unroll
        for (int q = 0; q < 8; q++) si[q] = __ldg(&csrsrc_buf[j + q]);
        if constexpr (V == 4) {
            uint2 r[8];
            #pragma unroll
            for (int q = 0; q < 8; q++)
                r[q] = __ldg((const uint2*)(G + (size_t)si[q] * D) + lane);
            half2 sx0 = __hadd2(__hadd2(*(half2*)&r[0].x, *(half2*)&r[1].x),
                                __hadd2(*(half2*)&r[2].x, *(half2*)&r[3].x));
            half2 sy0 = __hadd2(__hadd2(*(half2*)&r[0].y, *(half2*)&r[1].y),
                                __hadd2(*(half2*)&r[2].y, *(half2*)&r[3].y));
            half2 sx1 = __hadd2(__hadd2(*(half2*)&r[4].x, *(half2*)&r[5].x),
                                __hadd2(*(half2*)&r[6].x, *(half2*)&r[7].x));
            half2 sy1 = __hadd2(__hadd2(*(half2*)&r[4].y, *(half2*)&r[5].y),
                                __hadd2(*(half2*)&r[6].y, *(half2*)&r[7].y));
            float2 fx0 = __half22float2(sx0), fy0 = __half22float2(sy0);
            float2 fx1 = __half22float2(sx1), fy1 = __half22float2(sy1);
            acc[0] += fx0.x + fx1.x; acc[1] += fx0.y + fx1.y;
            acc[2] += fy0.x + fy1.x; acc[3] += fy0.y + fy1.y;
        } else {
            uint32_t r[8];
            #pragma unroll
            for (int q = 0; q < 8; q++)
                r[q] = __ldg((const uint32_t*)(G + (size_t)si[q] * D) + lane);
            half2 s0h = __hadd2(__hadd2(*(half2*)&r[0], *(half2*)&r[1]),
                                __hadd2(*(half2*)&r[2], *(half2*)&r[3]));
            half2 s1h = __hadd2(__hadd2(*(half2*)&r[4], *(half2*)&r[5]),
                                __hadd2(*(half2*)&r[6], *(half2*)&r[7]));
            float2 f0 = __half22float2(s0h), f1 = __half22float2(s1h);
            acc[0] += f0.x + f1.x; acc[1] += f0.y + f1.y;
        }
    }
    for (; j + 3 < s1; j += 4) {
        int sa = __ldg(&csrsrc_buf[j]);
        int sb = __ldg(&csrsrc_buf[j + 1]);
        int sc = __ldg(&csrsrc_buf[j + 2]);
        int sd = __ldg(&csrsrc_buf[j + 3]);
        if constexpr (V == 4) {
            uint2 a = __ldg((const uint2*)(G + (size_t)sa * D) + lane);
            uint2 b = __ldg((const uint2*)(G + (size_t)sb * D) + lane);
            uint2 c = __ldg((const uint2*)(G + (size_t)sc * D) + lane);
            uint2 d = __ldg((const uint2*)(G + (size_t)sd * D) + lane);
            half2 sx = __hadd2(__hadd2(*(half2*)&a.x, *(half2*)&b.x),
                               __hadd2(*(half2*)&c.x, *(half2*)&d.x));
            half2 sy = __hadd2(__hadd2(*(half2*)&a.y, *(half2*)&b.y),
                               __hadd2(*(half2*)&c.y, *(half2*)&d.y));
            float2 fx = __half22float2(sx);
            float2 fy = __half22float2(sy);
            acc[0] += fx.x; acc[1] += fx.y; acc[2] += fy.x; acc[3] += fy.y;
        } else {
            uint32_t a = __ldg((const uint32_t*)(G + (size_t)sa * D) + lane);
            uint32_t b = __ldg((const uint32_t*)(G + (size_t)sb * D) + lane);
            uint32_t c = __ldg((const uint32_t*)(G + (size_t)sc * D) + lane);
            uint32_t d = __ldg((const uint32_t*)(G + (size_t)sd * D) + lane);
            half2 sx = __hadd2(__hadd2(*(half2*)&a, *(half2*)&b),
                               __hadd2(*(half2*)&c, *(half2*)&d));
            float2 fx = __half22float2(sx);
            acc[0] += fx.x; acc[1] += fx.y;
        }
    }
    for (; j < s1; j++) {
        int s = __ldg(&csrsrc_buf[j]);
        if constexpr (V == 4) {
            uint2 a = __ldg((const uint2*)(G + (size_t)s * D) + lane);
            float2 f0 = __half22float2(*(half2*)&a.x), f1 = __half22float2(*(half2*)&a.y);
            acc[0] += f0.x; acc[1] += f0.y; acc[2] += f1.x; acc[3] += f1.y;
        } else {
            uint32_t a = __ldg((const uint32_t*)(G + (size_t)s * D) + lane);
            float2 f = __half22float2(*(half2*)&a);
            acc[0] += f.x; acc[1] += f.y;
        }
    }

    float di = dinv_buf[wid];
    if constexpr (V == 4) {
        float4 b = __ldg((const float4*)bias + lane);
        float o0 = acc[0] * di + b.x, o1 = acc[1] * di + b.y;
        float o2 = acc[2] * di + b.z, o3 = acc[3] * di + b.w;
        if (RELU) {
            o0 = fmaxf(o0, 0.f); o1 = fmaxf(o1, 0.f);
            o2 = fmaxf(o2, 0.f); o3 = fmaxf(o3, 0.f);
        }
        if constexpr (sizeof(TOUT) == 2) {
            __half* op = (__half*)OUT + (size_t)wid * D + lane * 4;
            *(half2*)op = __floats2half2_rn(o0, o1);
            *(half2*)(op + 2) = __floats2half2_rn(o2, o3);
        } else {
            float* op = (float*)OUT + (size_t)wid * D + lane * 4;
            *(float4*)op = make_float4(o0, o1, o2, o3);
        }
    } else {
        float2 b = __ldg((const float2*)bias + lane);
        float o0 = acc[0] * di + b.x, o1 = acc[1] * di + b.y;
        if (RELU) { o0 = fmaxf(o0, 0.f); o1 = fmaxf(o1, 0.f); }
        if constexpr (sizeof(TOUT) == 2) {
            __half* op = (__half*)OUT + (size_t)wid * D + lane * 2;
            *(half2*)op = __floats2half2_rn(o0, o1);
        } else {
            float* op = (float*)OUT + (size_t)wid * D + lane * 2;
            *(float2*)op = make_float2(o0, o1);
        }
    }
}

// ------------------------------- launch ------------------------------------

extern "C" void kernel_launch(void* const* d_in, const int* in_sizes, int n_in,
                              void* d_out, int out_size) {
    const float* x  = (const float*)d_in[0];
    const int*   ei = (const int*)d_in[1];
    const float* W1 = (const float*)d_in[2];
    const float* b1 = (const float*)d_in[3];
    const float* W2 = (const float*)d_in[4];
    const float* b2 = (const float*)d_in[5];
    const float* W3 = (const float*)d_in[6];
    const float* b3 = (const float*)d_in[7];

    int n = in_sizes[0] / 128;
    int e = in_sizes[1] / 2;
    const int* src = ei;
    const int* dst = ei + e;

    __half *g, *agg, *wt1, *wt2, *wt3;
    cudaGetSymbolAddress((void**)&g, g_buf);
    cudaGetSymbolAddress((void**)&agg, agg_buf);
    cudaGetSymbolAddress((void**)&wt1, wt1_buf);
    cudaGetSymbolAddress((void**)&wt2, wt2_buf);
    cudaGetSymbolAddress((void**)&wt3, wt3_buf);
    float* out = (float*)d_out;

    int nb = (n + 255) / 256;
    int eb = (e + 255) / 256;
    int scan_blocks = (n + SCAN_B - 1) / SCAN_B;

    constexpr int SMEM1 = (128 * 136 + 1 * 64 * 136) * 2;
    constexpr int SMEM2 = (128 * 136 + 2 * 64 * 136) * 2;
    constexpr int SMEM3 = (64 * 136 + 2 * 128 * 136) * 2;
    cudaFuncSetAttribute(k_gemm_tc<128, float>,  cudaFuncAttributeMaxDynamicSharedMemorySize, SMEM1);
    cudaFuncSetAttribute(k_gemm_tc<128, __half>, cudaFuncAttributeMaxDynamicSharedMemorySize, SMEM2);
    cudaFuncSetAttribute(k_gemm_tc<64,  __half>, cudaFuncAttributeMaxDynamicSharedMemorySize, SMEM3);

    int tiles128 = (n + 63) / 64;
    int tiles64  = (n + 127) / 128;
    int grid128 = tiles128 < 444 ? tiles128 : 444;
    int grid64  = tiles64  < 296 ? tiles64  : 296;

    // Single stream; GEMM1 is launch #4 (ncu captures launch 4).
    k_prep<<<nb, 256>>>(W1, W2, W3, n);                                     // 1
    k_hist<<<eb, 256>>>(dst, e);                                            // 2
    k_blocksum_dinv<<<scan_blocks, SCAN_B>>>(n);                            // 3
    k_gemm_tc<128, float><<<grid128, 256, SMEM1>>>(x, wt1, g, n, tiles128); // 4
    k_scan_blocksums<<<1, MAX_SCAN_BLOCKS>>>(scan_blocks, n, e);
    k_block_scan<<<scan_blocks, SCAN_B>>>(n);
    k_scatter<<<eb, 256>>>(src, dst, e);

    int agg_blocks = (n * 32 + 255) / 256;

    k_aggregate<128, true, __half><<<agg_blocks, 256>>>(g, b1, agg, n);

    k_gemm_tc<128, __half><<<grid128, 256, SMEM2>>>(agg, wt2, g, n, tiles128);
    k_aggregate<128, true, __half><<<agg_blocks, 256>>>(g, b2, agg, n);

    k_gemm_tc<64, __half><<<grid64, 256, SMEM3>>>(agg, wt3, g, n, tiles64);
    k_aggregate<64, false, float><<<agg_blocks, 256>>>(g, b3, out, n);
}

// round 13
// speedup vs baseline: 1.1443x; 1.0021x over previous
#include <cuda_runtime.h>
#include <cuda_fp16.h>
#include <cstddef>
#include <cstdint>

// ---------------------------------------------------------------------------
// GCN 3-layer encoder, fp16 pipeline, single-stream schedule.
//   per layer: g = (act(in) @ W) * dinv[row]   (fp16 MMA, fp32 accum)
//              out_i = dinv_i * (sum_{e: dst=i} g[src_e] + g_i) + b  [+ReLU]
// Persistent-block GEMMs with B (W) fragments hoisted into registers once per
// block — B ldmatrix removed from the tile loop (halves smem read traffic).
// Aggregation: unroll-8 gathers, fp16 HADD2 trees into fp32 accumulators.
// ---------------------------------------------------------------------------

#define N_MAX 100000
#define E_MAX 1600000
#define SCAN_B 1024
#define MAX_SCAN_BLOCKS 128

__device__ __half g_buf[(size_t)N_MAX * 128];
__device__ __half agg_buf[(size_t)N_MAX * 128];
__device__ float dinv_buf[N_MAX];
__device__ int   deg_buf[N_MAX];
__device__ int   rowptr_buf[N_MAX + 1];
__device__ int   cursor_buf[N_MAX];
__device__ int   csrsrc_buf[E_MAX];
__device__ int   blocksum_buf[MAX_SCAN_BLOCKS];
__device__ __half wt1_buf[128 * 128];
__device__ __half wt2_buf[128 * 128];
__device__ __half wt3_buf[64 * 128];

// ---------------- prep: zero deg + W transposes -----------------------------

__global__ void k_prep(const float* __restrict__ W1, const float* __restrict__ W2,
                       const float* __restrict__ W3, int n) {
    int i = blockIdx.x * blockDim.x + threadIdx.x;
    if (i < n) deg_buf[i] = 0;
    if (i < 128 * 128) {
        int k = i >> 7, c = i & 127;
        wt1_buf[c * 128 + k] = __float2half_rn(__ldg(&W1[i]));
        wt2_buf[c * 128 + k] = __float2half_rn(__ldg(&W2[i]));
    }
    if (i < 128 * 64) {
        int k = i >> 6, c = i & 63;
        wt3_buf[c * 128 + k] = __float2half_rn(__ldg(&W3[i]));
    }
}

// -------------------------------- CSR prep --------------------------------

__global__ void k_hist(const int* __restrict__ dst, int e) {
    int i = blockIdx.x * blockDim.x + threadIdx.x;
    if (i < e) atomicAdd(&deg_buf[dst[i]], 1);
}

__global__ __launch_bounds__(SCAN_B) void k_blocksum_dinv(int n) {
    __shared__ int wsum[32];
    int i = blockIdx.x * SCAN_B + threadIdx.x;
    int v = 0;
    if (i < n) {
        v = deg_buf[i];
        dinv_buf[i] = rsqrtf((float)v + 1.0f);
    }
    int s = v;
    #pragma unroll
    for (int off = 16; off > 0; off >>= 1)
        s += __shfl_down_sync(0xffffffffu, s, off);
    int lane = threadIdx.x & 31, w = threadIdx.x >> 5;
    if (lane == 0) wsum[w] = s;
    __syncthreads();
    if (w == 0) {
        int t = wsum[lane];
        #pragma unroll
        for (int off = 16; off > 0; off >>= 1)
            t += __shfl_down_sync(0xffffffffu, t, off);
        if (lane == 0) blocksum_buf[blockIdx.x] = t;
    }
}

__global__ void k_scan_blocksums(int nblocks, int n, int e) {
    __shared__ int wsum[4];
    int t = threadIdx.x;
    int v = (t < nblocks) ? blocksum_buf[t] : 0;
    int lane = t & 31, w = t >> 5;
    int s = v;
    #pragma unroll
    for (int off = 1; off < 32; off <<= 1) {
        int x = __shfl_up_sync(0xffffffffu, s, off);
        if (lane >= off) s += x;
    }
    if (lane == 31) wsum[w] = s;
    __syncthreads();
    int base = 0;
    #pragma unroll
    for (int k = 0; k < 4; k++) base += (k < w) ? wsum[k] : 0;
    if (t < nblocks) blocksum_buf[t] = base + s - v;
    if (t == 0) rowptr_buf[n] = e;
}

__global__ __launch_bounds__(SCAN_B) void k_block_scan(int n) {
    __shared__ int wsum[32];
    int i = blockIdx.x * SCAN_B + threadIdx.x;
    int v = (i < n) ? deg_buf[i] : 0;
    int lane = threadIdx.x & 31, w = threadIdx.x >> 5;
    int s = v;
    #pragma unroll
    for (int off = 1; off < 32; off <<= 1) {
        int x = __shfl_up_sync(0xffffffffu, s, off);
        if (lane >= off) s += x;
    }
    if (lane == 31) wsum[w] = s;
    __syncthreads();
    if (w == 0) {
        int ws = wsum[lane];
        #pragma unroll
        for (int off = 1; off < 32; off <<= 1) {
            int x = __shfl_up_sync(0xffffffffu, ws, off);
            if (lane >= off) ws += x;
        }
        wsum[lane] = ws;
    }
    __syncthreads();
    int warpBase = (w > 0) ? wsum[w - 1] : 0;
    if (i < n) {
        int p = blocksum_buf[blockIdx.x] + warpBase + (s - v);
        rowptr_buf[i] = p;
        cursor_buf[i] = p;
    }
}

__global__ void k_scatter(const int* __restrict__ src, const int* __restrict__ dst, int e) {
    int i = blockIdx.x * blockDim.x + threadIdx.x;
    if (i < e) {
        int d = dst[i];
        int pos = atomicAdd(&cursor_buf[d], 1);
        csrsrc_buf[pos] = src[i];
    }
}

// ----------------------- fp16 tensor-core GEMM -----------------------------
// Persistent blocks; W staged once to smem, then each warp hoists its full B
// slice (32 cols x 128 k) into 64 registers. Tile loop: A ldmatrix + MMA only.

__device__ __forceinline__ void ldsm_x4(uint32_t& r0, uint32_t& r1,
                                        uint32_t& r2, uint32_t& r3, uint32_t addr) {
    asm volatile("ldmatrix.sync.aligned.m8n8.x4.shared.b16 {%0,%1,%2,%3}, [%4];"
                 : "=r"(r0), "=r"(r1), "=r"(r2), "=r"(r3) : "r"(addr));
}

template <int DOUT, typename TIN>
__global__ __launch_bounds__(256, 2) void k_gemm_tc(const TIN* __restrict__ X,
                                                    const __half* __restrict__ Wt,
                                                    __half* __restrict__ G,
                                                    int n, int tiles) {
    constexpr bool HALF_IN = (sizeof(TIN) == 2);
    constexpr int DIN = 128;
    constexpr int WN = DOUT / 32;
    constexpr int WM = 8 / WN;
    constexpr int MB = WM * 32;
    constexpr int XS = 136;
    constexpr int WKS = 136;
    constexpr int XTILE = MB * XS;
    constexpr int NBUF = HALF_IN ? 2 : 1;
    constexpr int NKS = DIN / 16;    // 8

    extern __shared__ __half hsm[];
    __half* Ws = hsm;
    __half* Xb[2] = { hsm + DOUT * WKS,
                      hsm + DOUT * WKS + (NBUF == 2 ? XTILE : 0) };

    int t = threadIdx.x;
    int warp = t >> 5, lane = t & 31;
    int wm = warp / WN, wn = warp % WN;
    int g = lane >> 2, tg = lane & 3;

    #pragma unroll
    for (int i = t * 8; i < DOUT * DIN; i += 256 * 8) {
        int c = i >> 7, k = i & 127;
        uint4 v = __ldg((const uint4*)(Wt + i));
        *(uint4*)&Ws[c * WKS + k] = v;
    }

    auto stage_async = [&](int tile, __half* buf) {
        int rowBase = tile * MB;
        #pragma unroll
        for (int i = t * 8; i < MB * DIN; i += 256 * 8) {
            int r = i >> 7, c = i & 127;
            int row = rowBase + r;
            uint32_t saddr = (uint32_t)__cvta_generic_to_shared(&buf[r * XS + c]);
            const __half* gp = (const __half*)X + (size_t)(row < n ? row : 0) * DIN + c;
            int sz = (row < n) ? 16 : 0;
            asm volatile("cp.async.cg.shared.global [%0], [%1], 16, %2;"
                         :: "r"(saddr), "l"(gp), "r"(sz) : "memory");
        }
        asm volatile("cp.async.commit_group;" ::: "memory");
    };
    auto stage_f32 = [&](int tile, __half* buf) {
        int rowBase = tile * MB;
        #pragma unroll
        for (int i = t * 8; i < MB * DIN; i += 256 * 8) {
            int r = i >> 7, c = i & 127;
            int row = rowBase + r;
            uint4 u;
            if (row < n) {
                const float* xp = (const float*)X + (size_t)row * DIN + c;
                float4 v0 = __ldg((const float4*)xp);
                float4 v1 = __ldg((const float4*)(xp + 4));
                half2 h0 = __floats2half2_rn(v0.x, v0.y);
                half2 h1 = __floats2half2_rn(v0.z, v0.w);
                half2 h2 = __floats2half2_rn(v1.x, v1.y);
                half2 h3 = __floats2half2_rn(v1.z, v1.w);
                u = make_uint4(*(uint32_t*)&h0, *(uint32_t*)&h1,
                               *(uint32_t*)&h2, *(uint32_t*)&h3);
            } else u = make_uint4(0u, 0u, 0u, 0u);
            *(uint4*)&buf[r * XS + c] = u;
        }
    };

    uint32_t ws_base = (uint32_t)__cvta_generic_to_shared(Ws);
    uint32_t b_addr = ws_base + (uint32_t)(((wn * 32 + lane) * WKS) * 2);

    int tile = blockIdx.x;
    int cur = 0;
    if (HALF_IN && tile < tiles) stage_async(tile, Xb[0]);

    // W visible to all threads; hoist B fragments into registers (tile-invariant).
    __syncthreads();
    uint32_t breg0[NKS][4], breg1[NKS][4];
    #pragma unroll
    for (int ks = 0; ks < NKS; ks++) {
        uint32_t koff = (uint32_t)(ks * 32);
        ldsm_x4(breg0[ks][0], breg0[ks][1], breg0[ks][2], breg0[ks][3], b_addr + koff);
        ldsm_x4(breg1[ks][0], breg1[ks][1], breg1[ks][2], breg1[ks][3], b_addr + koff + 16);
    }

    for (; tile < tiles; tile += gridDim.x) {
        if constexpr (HALF_IN) {
            int nxt = tile + gridDim.x;
            if (nxt < tiles) stage_async(nxt, Xb[cur ^ 1]);
            if (nxt < tiles)
                asm volatile("cp.async.wait_group 1;" ::: "memory");
            else
                asm volatile("cp.async.wait_group 0;" ::: "memory");
            __syncthreads();
        } else {
            __syncthreads();
            stage_f32(tile, Xb[0]);
            __syncthreads();
        }

        __half* Xs = Xb[cur];
        uint32_t xs_base = (uint32_t)__cvta_generic_to_shared(Xs);
        uint32_t a_addr0 = xs_base + (uint32_t)(((wm * 32 + (lane & 15)) * XS + ((lane >> 4) << 3)) * 2);
        uint32_t a_addr1 = a_addr0 + (uint32_t)(16 * XS * 2);

        float acc[2][4][4];
        #pragma unroll
        for (int a = 0; a < 2; a++)
            #pragma unroll
            for (int u = 0; u < 4; u++)
                #pragma unroll
                for (int k = 0; k < 4; k++) acc[a][u][k] = 0.f;

        #pragma unroll
        for (int ks = 0; ks < NKS; ks++) {
            uint32_t koff = (uint32_t)(ks * 32);
            uint32_t a[2][4];
            ldsm_x4(a[0][0], a[0][1], a[0][2], a[0][3], a_addr0 + koff);
            ldsm_x4(a[1][0], a[1][1], a[1][2], a[1][3], a_addr1 + koff);
            #pragma unroll
            for (int tt = 0; tt < 2; tt++)
                #pragma unroll
                for (int u = 0; u < 4; u++) {
                    asm volatile(
                        "mma.sync.aligned.m16n8k16.row.col.f32.f16.f16.f32 "
                        "{%0,%1,%2,%3}, {%4,%5,%6,%7}, {%8,%9}, {%0,%1,%2,%3};"
                        : "+f"(acc[tt][u][0]), "+f"(acc[tt][u][1]),
                          "+f"(acc[tt][u][2]), "+f"(acc[tt][u][3])
                        : "r"(a[tt][0]), "r"(a[tt][1]), "r"(a[tt][2]), "r"(a[tt][3]),
                          "r"(breg0[ks][u]), "r"(breg1[ks][u]));
                }
        }

        int rowBase = tile * MB;
        #pragma unroll
        for (int tt = 0; tt < 2; tt++) {
            int r0 = rowBase + wm * 32 + tt * 16 + g;
            int r1 = r0 + 8;
            int cbase = wn * 32 + 2 * tg;
            if (r0 < n) {
                float di = dinv_buf[r0];
                #pragma unroll
                for (int u = 0; u < 4; u++) {
                    half2 h = __floats2half2_rn(acc[tt][u][0] * di, acc[tt][u][1] * di);
                    *(half2*)(G + (size_t)r0 * DOUT + cbase + u * 8) = h;
                }
            }
            if (r1 < n) {
                float di = dinv_buf[r1];
                #pragma unroll
                for (int u = 0; u < 4; u++) {
                    half2 h = __floats2half2_rn(acc[tt][u][2] * di, acc[tt][u][3] * di);
                    *(half2*)(G + (size_t)r1 * DOUT + cbase + u * 8) = h;
                }
            }
        }
        if constexpr (HALF_IN) {
            __syncthreads();
            cur ^= 1;
        }
    }
}

// ------------------------------ Aggregation --------------------------------

template <int D, bool RELU, typename TOUT>
__global__ __launch_bounds__(256) void k_aggregate(const __half* __restrict__ G,
                                                   const float* __restrict__ bias,
                                                   TOUT* __restrict__ OUT, int n) {
    int wid = (blockIdx.x * blockDim.x + threadIdx.x) >> 5;
    int lane = threadIdx.x & 31;
    if (wid >= n) return;
    constexpr int V = D / 32;

    float acc[V];
    if constexpr (V == 4) {
        uint2 a = *(const uint2*)(G + (size_t)wid * D + lane * 4);
        float2 f0 = __half22float2(*(half2*)&a.x);
        float2 f1 = __half22float2(*(half2*)&a.y);
        acc[0] = f0.x; acc[1] = f0.y; acc[2] = f1.x; acc[3] = f1.y;
    } else {
        uint32_t a = *(const uint32_t*)(G + (size_t)wid * D + lane * 2);
        float2 f = __half22float2(*(half2*)&a);
        acc[0] = f.x; acc[1] = f.y;
    }

    int s0 = rowptr_buf[wid];
    int s1 = rowptr_buf[wid + 1];

    int j = s0;
    for (; j + 7 < s1; j += 8) {
        int si[8];
        #pragma unroll
        for (int q = 0; q < 8; q++) si[q] = __ldg(&csrsrc_buf[j + q]);
        if constexpr (V == 4) {
            uint2 r[8];
            #pragma unroll
            for (int q = 0; q < 8; q++)
                r[q] = __ldg((const uint2*)(G + (size_t)si[q] * D) + lane);
            half2 sx0 = __hadd2(__hadd2(*(half2*)&r[0].x, *(half2*)&r[1].x),
                                __hadd2(*(half2*)&r[2].x, *(half2*)&r[3].x));
            half2 sy0 = __hadd2(__hadd2(*(half2*)&r[0].y, *(half2*)&r[1].y),
                                __hadd2(*(half2*)&r[2].y, *(half2*)&r[3].y));
            half2 sx1 = __hadd2(__hadd2(*(half2*)&r[4].x, *(half2*)&r[5].x),
                                __hadd2(*(half2*)&r[6].x, *(half2*)&r[7].x));
            half2 sy1 = __hadd2(__hadd2(*(half2*)&r[4].y, *(half2*)&r[5].y),
                                __hadd2(*(half2*)&r[6].y, *(half2*)&r[7].y));
            float2 fx0 = __half22float2(sx0), fy0 = __half22float2(sy0);
            float2 fx1 = __half22float2(sx1), fy1 = __half22float2(sy1);
            acc[0] += fx0.x + fx1.x; acc[1] += fx0.y + fx1.y;
            acc[2] += fy0.x + fy1.x; acc[3] += fy0.y + fy1.y;
        } else {
            uint32_t r[8];
            #pragma unroll
            for (int q = 0; q < 8; q++)
                r[q] = __ldg((const uint32_t*)(G + (size_t)si[q] * D) + lane);
            half2 s0h = __hadd2(__hadd2(*(half2*)&r[0], *(half2*)&r[1]),
                                __hadd2(*(half2*)&r[2], *(half2*)&r[3]));
            half2 s1h = __hadd2(__hadd2(*(half2*)&r[4], *(half2*)&r[5]),
                                __hadd2(*(half2*)&r[6], *(half2*)&r[7]));
            float2 f0 = __half22float2(s0h), f1 = __half22float2(s1h);
            acc[0] += f0.x + f1.x; acc[1] += f0.y + f1.y;
        }
    }
    for (; j + 3 < s1; j += 4) {
        int sa = __ldg(&csrsrc_buf[j]);
        int sb = __ldg(&csrsrc_buf[j + 1]);
        int sc = __ldg(&csrsrc_buf[j + 2]);
        int sd = __ldg(&csrsrc_buf[j + 3]);
        if constexpr (V == 4) {
            uint2 a = __ldg((const uint2*)(G + (size_t)sa * D) + lane);
            uint2 b = __ldg((const uint2*)(G + (size_t)sb * D) + lane);
            uint2 c = __ldg((const uint2*)(G + (size_t)sc * D) + lane);
            uint2 d = __ldg((const uint2*)(G + (size_t)sd * D) + lane);
            half2 sx = __hadd2(__hadd2(*(half2*)&a.x, *(half2*)&b.x),
                               __hadd2(*(half2*)&c.x, *(half2*)&d.x));
            half2 sy = __hadd2(__hadd2(*(half2*)&a.y, *(half2*)&b.y),
                               __hadd2(*(half2*)&c.y, *(half2*)&d.y));
            float2 fx = __half22float2(sx);
            float2 fy = __half22float2(sy);
            acc[0] += fx.x; acc[1] += fx.y; acc[2] += fy.x; acc[3] += fy.y;
        } else {
            uint32_t a = __ldg((const uint32_t*)(G + (size_t)sa * D) + lane);
            uint32_t b = __ldg((const uint32_t*)(G + (size_t)sb * D) + lane);
            uint32_t c = __ldg((const uint32_t*)(G + (size_t)sc * D) + lane);
            uint32_t d = __ldg((const uint32_t*)(G + (size_t)sd * D) + lane);
            half2 sx = __hadd2(__hadd2(*(half2*)&a, *(half2*)&b),
                               __hadd2(*(half2*)&c, *(half2*)&d));
            float2 fx = __half22float2(sx);
            acc[0] += fx.x; acc[1] += fx.y;
        }
    }
    for (; j < s1; j++) {
        int s = __ldg(&csrsrc_buf[j]);
        if constexpr (V == 4) {
            uint2 a = __ldg((const uint2*)(G + (size_t)s * D) + lane);
            float2 f0 = __half22float2(*(half2*)&a.x), f1 = __half22float2(*(half2*)&a.y);
            acc[0] += f0.x; acc[1] += f0.y; acc[2] += f1.x; acc[3] += f1.y;
        } else {
            uint32_t a = __ldg((const uint32_t*)(G + (size_t)s * D) + lane);
            float2 f = __half22float2(*(half2*)&a);
            acc[0] += f.x; acc[1] += f.y;
        }
    }

    float di = dinv_buf[wid];
    if constexpr (V == 4) {
        float4 b = __ldg((const float4*)bias + lane);
        float o0 = acc[0] * di + b.x, o1 = acc[1] * di + b.y;
        float o2 = acc[2] * di + b.z, o3 = acc[3] * di + b.w;
        if (RELU) {
            o0 = fmaxf(o0, 0.f); o1 = fmaxf(o1, 0.f);
            o2 = fmaxf(o2, 0.f); o3 = fmaxf(o3, 0.f);
        }
        if constexpr (sizeof(TOUT) == 2) {
            __half* op = (__half*)OUT + (size_t)wid * D + lane * 4;
            *(half2*)op = __floats2half2_rn(o0, o1);
            *(half2*)(op + 2) = __floats2half2_rn(o2, o3);
        } else {
            float* op = (float*)OUT + (size_t)wid * D + lane * 4;
            *(float4*)op = make_float4(o0, o1, o2, o3);
        }
    } else {
        float2 b = __ldg((const float2*)bias + lane);
        float o0 = acc[0] * di + b.x, o1 = acc[1] * di + b.y;
        if (RELU) { o0 = fmaxf(o0, 0.f); o1 = fmaxf(o1, 0.f); }
        if constexpr (sizeof(TOUT) == 2) {
            __half* op = (__half*)OUT + (size_t)wid * D + lane * 2;
            *(half2*)op = __floats2half2_rn(o0, o1);
        } else {
            float* op = (float*)OUT + (size_t)wid * D + lane * 2;
            *(float2*)op = make_float2(o0, o1);
        }
    }
}

// ------------------------------- launch ------------------------------------

extern "C" void kernel_launch(void* const* d_in, const int* in_sizes, int n_in,
                              void* d_out, int out_size) {
    const float* x  = (const float*)d_in[0];
    const int*   ei = (const int*)d_in[1];
    const float* W1 = (const float*)d_in[2];
    const float* b1 = (const float*)d_in[3];
    const float* W2 = (const float*)d_in[4];
    const float* b2 = (const float*)d_in[5];
    const float* W3 = (const float*)d_in[6];
    const float* b3 = (const float*)d_in[7];

    int n = in_sizes[0] / 128;
    int e = in_sizes[1] / 2;
    const int* src = ei;
    const int* dst = ei + e;

    __half *g, *agg, *wt1, *wt2, *wt3;
    cudaGetSymbolAddress((void**)&g, g_buf);
    cudaGetSymbolAddress((void**)&agg, agg_buf);
    cudaGetSymbolAddress((void**)&wt1, wt1_buf);
    cudaGetSymbolAddress((void**)&wt2, wt2_buf);
    cudaGetSymbolAddress((void**)&wt3, wt3_buf);
    float* out = (float*)d_out;

    int nb = (n + 255) / 256;
    int eb = (e + 255) / 256;
    int scan_blocks = (n + SCAN_B - 1) / SCAN_B;

    constexpr int SMEM1 = (128 * 136 + 1 * 64 * 136) * 2;
    constexpr int SMEM2 = (128 * 136 + 2 * 64 * 136) * 2;
    constexpr int SMEM3 = (64 * 136 + 2 * 128 * 136) * 2;
    cudaFuncSetAttribute(k_gemm_tc<128, float>,  cudaFuncAttributeMaxDynamicSharedMemorySize, SMEM1);
    cudaFuncSetAttribute(k_gemm_tc<128, __half>, cudaFuncAttributeMaxDynamicSharedMemorySize, SMEM2);
    cudaFuncSetAttribute(k_gemm_tc<64,  __half>, cudaFuncAttributeMaxDynamicSharedMemorySize, SMEM3);

    int tiles128 = (n + 63) / 64;
    int tiles64  = (n + 127) / 128;
    int grid128 = tiles128 < 296 ? tiles128 : 296;   // 2 blocks/SM (reg-capped)
    int grid64  = tiles64  < 296 ? tiles64  : 296;

    // Single stream; GEMM1 is launch #4 (ncu captures launch 4).
    k_prep<<<nb, 256>>>(W1, W2, W3, n);                                     // 1
    k_hist<<<eb, 256>>>(dst, e);                                            // 2
    k_blocksum_dinv<<<scan_blocks, SCAN_B>>>(n);                            // 3
    k_gemm_tc<128, float><<<grid128, 256, SMEM1>>>(x, wt1, g, n, tiles128); // 4
    k_scan_blocksums<<<1, MAX_SCAN_BLOCKS>>>(scan_blocks, n, e);
    k_block_scan<<<scan_blocks, SCAN_B>>>(n);
    k_scatter<<<eb, 256>>>(src, dst, e);

    int agg_blocks = (n * 32 + 255) / 256;

    k_aggregate<128, true, __half><<<agg_blocks, 256>>>(g, b1, agg, n);

    k_gemm_tc<128, __half><<<grid128, 256, SMEM2>>>(agg, wt2, g, n, tiles128);
    k_aggregate<128, true, __half><<<agg_blocks, 256>>>(g, b2, agg, n);

    k_gemm_tc<64, __half><<<grid64, 256, SMEM3>>>(agg, wt3, g, n, tiles64);
    k_aggregate<64, false, float><<<agg_blocks, 256>>>(g, b3, out, n);
}